// round 3
// baseline (speedup 1.0000x reference)
#include <cuda_runtime.h>
#include <math.h>

// Problem constants (fixed shapes)
#define CC      128          // channels
#define TN      64           // voxels per tile
#define NCOND   4
#define NHEADS  8
#define NVOX    32768        // 32*32*32
#define NTILES  512          // NVOX / TN
#define NB      2
#define NGROUPS 8
#define GSIZE   16           // channels per group

// shared memory layout (floats)
#define SW   (CC*CC)         // 16384 — one weight matrix (transposed: [k][co])
#define SY   (CC*TN)         // 8192  — activation tile
#define SSP  (16*TN)         // 1024  — partial scores (cy, n)
#define SHN  (NHEADS*TN)     // 512   — per-(head,voxel) softmax state

typedef unsigned long long ull;

// scratch (no allocations allowed)
__device__ float  g_wT[4][CC*CC];          // transposed weights: Wq,Wk,Wv,Wo as [k][co]
__device__ float  g_sum[NB*NGROUPS*NTILES];
__device__ float  g_sq [NB*NGROUPS*NTILES];
__device__ float2 g_stats[NB*NGROUPS];

// ---------------------------------------------------------------------------
// packed f32x2 helpers (Blackwell FFMA2 path)
// ---------------------------------------------------------------------------
__device__ __forceinline__ ull dup2(float a) {
    ull r; asm("mov.b64 %0, {%1, %1};" : "=l"(r) : "f"(a)); return r;
}
__device__ __forceinline__ ull pack2(float a, float b) {
    ull r; asm("mov.b64 %0, {%1, %2};" : "=l"(r) : "f"(a), "f"(b)); return r;
}
__device__ __forceinline__ float2 unpack2(ull v) {
    float2 r; asm("mov.b64 {%0, %1}, %2;" : "=f"(r.x), "=f"(r.y) : "l"(v)); return r;
}
__device__ __forceinline__ void ffma2(ull& d, ull a, ull b) {
    asm("fma.rn.f32x2 %0, %1, %2, %0;" : "+l"(d) : "l"(a), "l"(b));
}
__device__ __forceinline__ ull ffma2_3(ull a, ull b, ull c) {
    ull d; asm("fma.rn.f32x2 %0, %1, %2, %3;" : "=l"(d) : "l"(a), "l"(b), "l"(c)); return d;
}
__device__ __forceinline__ ull fmul2(ull a, ull b) {
    ull d; asm("mul.rn.f32x2 %0, %1, %2;" : "=l"(d) : "l"(a), "l"(b)); return d;
}

// ---------------------------------------------------------------------------
// Kernel 0: transpose the 4 weight matrices into [k][co] layout (runs once per
// launch; ~3us). Makes channel pairs (co, co+1) contiguous for b64 loads.
// ---------------------------------------------------------------------------
extern "C" __global__ void transpose_w(const float* __restrict__ wq,
                                       const float* __restrict__ wk,
                                       const float* __restrict__ wv,
                                       const float* __restrict__ wo) {
    int idx = blockIdx.x * 256 + threadIdx.x;   // 0..65535
    int m = idx >> 14;
    int e = idx & 16383;
    int r = e >> 7, c = e & 127;                // src row r, col c
    const float* src = (m == 0) ? wq : (m == 1) ? wk : (m == 2) ? wv : wo;
    g_wT[m][c*CC + r] = src[r*CC + c];
}

// ---------------------------------------------------------------------------
// cooperative loaders
// ---------------------------------------------------------------------------
__device__ __forceinline__ void load_w_smem(float* dst, const float* __restrict__ src, int tid) {
    const float4* s4 = (const float4*)src;
    float4* d4 = (float4*)dst;
#pragma unroll
    for (int r = 0; r < 16; r++) {
        int idx = r*256 + tid;
        d4[idx] = s4[idx];
    }
}

__device__ __forceinline__ void load_tile(float* dst, const float* __restrict__ src, int tid) {
#pragma unroll
    for (int r = 0; r < 8; r++) {
        int idx = r*256 + tid;          // 0..2047
        int row = idx >> 4;
        int c4  = idx & 15;
        float4 v = *(const float4*)(src + (size_t)row*NVOX + c4*4);
        *(float4*)(dst + row*TN + c4*4) = v;
    }
}

// ---------------------------------------------------------------------------
// packed register-blocked GEMM: acc2[p][j] (+)= W[co0+2p..2p+1, :] @ Y[:, n0+j]
// wt: transposed weights [k][co] in smem (reads broadcast),
// Y [128][64] in smem. acc2 lanes = channel pair (co0+2p, co0+2p+1).
// 16 FFMA2 + 3 LDS.128 + 4 dup per k-step.
// ---------------------------------------------------------------------------
__device__ __forceinline__ void gemm_acc2(ull acc[4][4], const float* __restrict__ wt,
                                          const float* __restrict__ yb, int co0, int n0) {
    const float* wp = wt + co0;
    const float* yp = yb + n0;
#pragma unroll 4
    for (int k = 0; k < CC; k++) {
        float4 y = *(const float4*)(yp + k*TN);
        ulonglong2 wA = *(const ulonglong2*)(wp + k*CC);       // (co0,co0+1),(co0+2,co0+3)
        ulonglong2 wB = *(const ulonglong2*)(wp + k*CC + 4);   // (co0+4,co0+5),(co0+6,co0+7)
        ull y0 = dup2(y.x), y1 = dup2(y.y), y2 = dup2(y.z), y3 = dup2(y.w);
        ffma2(acc[0][0], wA.x, y0); ffma2(acc[0][1], wA.x, y1);
        ffma2(acc[0][2], wA.x, y2); ffma2(acc[0][3], wA.x, y3);
        ffma2(acc[1][0], wA.y, y0); ffma2(acc[1][1], wA.y, y1);
        ffma2(acc[1][2], wA.y, y2); ffma2(acc[1][3], wA.y, y3);
        ffma2(acc[2][0], wB.x, y0); ffma2(acc[2][1], wB.x, y1);
        ffma2(acc[2][2], wB.x, y2); ffma2(acc[2][3], wB.x, y3);
        ffma2(acc[3][0], wB.y, y0); ffma2(acc[3][1], wB.y, y1);
        ffma2(acc[3][2], wB.y, y2); ffma2(acc[3][3], wB.y, y3);
    }
}

__device__ __forceinline__ void init_bias2(ull acc[4][4], const float* __restrict__ bias, int co0) {
#pragma unroll
    for (int p = 0; p < 4; p++) {
        ull bv = pack2(__ldg(&bias[co0+2*p]), __ldg(&bias[co0+2*p+1]));
#pragma unroll
        for (int j = 0; j < 4; j++) acc[p][j] = bv;
    }
}

// ---------------------------------------------------------------------------
// Kernel 1: fused QKV projections + online-softmax cross-attention + O-proj
//           + residual; emits pre-GN output and per-(batch,group) partials.
// Block 256 thr; thread (cy=tid/16, nx=tid%16) owns channels [8cy,8cy+8) x
// voxels [4nx,4nx+4). Thread's channels sit in one head (h=cy/2); a warp's 32
// channels sit in one GN group (g = warp id).
// ---------------------------------------------------------------------------
extern "C" __global__ void __launch_bounds__(256, 1)
attn_fused(const float* __restrict__ skip, const float* __restrict__ dec,
           const float* __restrict__ bq, const float* __restrict__ bk,
           const float* __restrict__ bv,
           const float* __restrict__ bo,
           float* __restrict__ out)
{
    extern __shared__ float sm[];
    float* wtA  = sm;             // weight A: WqT -> WkT -> WoT
    float* wtB  = wtA + SW;       // weight B: WvT
    float* ybuf = wtB + SW;       // activation tile: X -> Y_c -> O_attn
    float* sp   = ybuf + SY;      // partial scores [16][64]
    float* ms   = sp + SSP;       // running max   [8][64]
    float* ls   = ms + SHN;       // running sumexp[8][64]
    float* cs   = ls + SHN;       // correction    [8][64]
    float* pp   = cs + SHN;       // p = exp(s-m)  [8][64]

    const int tid  = threadIdx.x;
    const int tile = blockIdx.x;
    const int b    = blockIdx.y;
    const int cy = tid >> 4, nx = tid & 15;
    const int co0 = cy*8, n0 = nx*4;
    const int h = cy >> 1;

    const size_t voxBase = (size_t)tile * TN;
    const float* decb  = dec  + (size_t)b*CC*NVOX + voxBase;
    const float* skipb = skip + (size_t)b*NCOND*CC*NVOX + voxBase;

    // Phase 0: X tile + WqT, init softmax state
    load_tile(ybuf, decb, tid);
    load_w_smem(wtA, g_wT[0], tid);
    ms[tid] = -INFINITY; ms[tid+256] = -INFINITY;
    ls[tid] = 0.0f;      ls[tid+256] = 0.0f;
    __syncthreads();

    // Q projection (kept packed in registers)
    ull q2[4][4];
    init_bias2(q2, bq, co0);
    gemm_acc2(q2, wtA, ybuf, co0, n0);

    ull oacc2[4][4];
#pragma unroll
    for (int p = 0; p < 4; p++)
#pragma unroll
        for (int j = 0; j < 4; j++) oacc2[p][j] = 0ull;

    __syncthreads();                       // done reading WqT (wtA) and X (ybuf)
    load_w_smem(wtA, g_wT[1], tid);        // WkT
    load_w_smem(wtB, g_wT[2], tid);        // WvT

    // cond loop with online softmax
    for (int c = 0; c < NCOND; c++) {
        __syncthreads();                   // ybuf free / weights staged
        load_tile(ybuf, skipb + (size_t)c*CC*NVOX, tid);
        __syncthreads();

        // K = Wk @ Y + bk, fused with partial score q.k
        ull kv2[4][4];
        init_bias2(kv2, bk, co0);
        gemm_acc2(kv2, wtA, ybuf, co0, n0);

        ull ps2[4] = {0ull, 0ull, 0ull, 0ull};
#pragma unroll
        for (int p = 0; p < 4; p++)
#pragma unroll
            for (int j = 0; j < 4; j++) ffma2(ps2[j], q2[p][j], kv2[p][j]);
#pragma unroll
        for (int j = 0; j < 4; j++) {
            float2 v = unpack2(ps2[j]);
            sp[cy*TN + n0 + j] = v.x + v.y;
        }
        __syncthreads();

        // softmax state update: 512 (head,voxel) items over 256 threads
#pragma unroll
        for (int t = tid; t < 2*256; t += 256) {
            int hh = t >> 6, nn = t & 63;
            float s  = (sp[(2*hh)*TN + nn] + sp[(2*hh+1)*TN + nn]) * 0.25f;
            float mo = ms[t];
            float mn = fmaxf(mo, s);
            float corr = __expf(mo - mn);
            float pv   = __expf(s - mn);
            ls[t] = ls[t]*corr + pv;
            ms[t] = mn;
            cs[t] = corr;
            pp[t] = pv;
        }
        __syncthreads();

        // V = Wv @ Y + bv (reuse kv2 registers)
        init_bias2(kv2, bv, co0);
        gemm_acc2(kv2, wtB, ybuf, co0, n0);

        // oacc = oacc*corr + p*V  (packed)
#pragma unroll
        for (int j = 0; j < 4; j++) {
            ull corr2 = dup2(cs[h*TN + n0 + j]);
            ull pv2   = dup2(pp[h*TN + n0 + j]);
#pragma unroll
            for (int p = 0; p < 4; p++)
                oacc2[p][j] = ffma2_3(oacc2[p][j], corr2, fmul2(pv2, kv2[p][j]));
        }
    }

    // finalize attention output -> ybuf; stage WoT
    __syncthreads();                       // everyone done with ybuf (V gemm)
#pragma unroll
    for (int j = 0; j < 4; j++) {
        float inv = 1.0f / ls[h*TN + n0 + j];
#pragma unroll
        for (int p = 0; p < 4; p++) {
            float2 o = unpack2(oacc2[p][j]);
            ybuf[(co0+2*p  )*TN + n0 + j] = o.x * inv;
            ybuf[(co0+2*p+1)*TN + n0 + j] = o.y * inv;
        }
    }
    load_w_smem(wtA, g_wT[3], tid);        // WoT (wtA free)
    __syncthreads();

    // O projection + bias + residual
    ull ov2[4][4];
    init_bias2(ov2, bo, co0);
    gemm_acc2(ov2, wtA, ybuf, co0, n0);

    float* outb = out + (size_t)b*CC*NVOX + voxBase;
    float s1 = 0.0f, s2 = 0.0f;
#pragma unroll
    for (int p = 0; p < 4; p++) {
        float4 r0 = *(const float4*)(decb + (size_t)(co0+2*p  )*NVOX + n0);
        float4 r1 = *(const float4*)(decb + (size_t)(co0+2*p+1)*NVOX + n0);
        float2 a0 = unpack2(ov2[p][0]);
        float2 a1 = unpack2(ov2[p][1]);
        float2 a2 = unpack2(ov2[p][2]);
        float2 a3 = unpack2(ov2[p][3]);
        float u0 = a0.x + r0.x, u1 = a1.x + r0.y, u2 = a2.x + r0.z, u3 = a3.x + r0.w;
        float w0 = a0.y + r1.x, w1 = a1.y + r1.y, w2 = a2.y + r1.z, w3 = a3.y + r1.w;
        *(float4*)(outb + (size_t)(co0+2*p  )*NVOX + n0) = make_float4(u0, u1, u2, u3);
        *(float4*)(outb + (size_t)(co0+2*p+1)*NVOX + n0) = make_float4(w0, w1, w2, w3);
        s1 += (u0 + u1) + (u2 + u3) + (w0 + w1) + (w2 + w3);
        s2 += fmaf(u0, u0, u1*u1) + fmaf(u2, u2, u3*u3)
            + fmaf(w0, w0, w1*w1) + fmaf(w2, w2, w3*w3);
    }

    // deterministic GroupNorm partials: whole warp belongs to group g = warp id
#pragma unroll
    for (int off = 16; off; off >>= 1) {
        s1 += __shfl_xor_sync(0xffffffffu, s1, off);
        s2 += __shfl_xor_sync(0xffffffffu, s2, off);
    }
    int warp = tid >> 5;
    if ((tid & 31) == 0) {
        int slot = (b*NGROUPS + warp)*NTILES + tile;
        g_sum[slot] = s1;
        g_sq[slot]  = s2;
    }
}

// ---------------------------------------------------------------------------
// Kernel 2: reduce per-tile partials into per-(batch,group) mean / rstd
// ---------------------------------------------------------------------------
extern "C" __global__ void gn_stats() {
    __shared__ float sh1[256], sh2[256];
    const int bg = blockIdx.x;        // 0..15
    const int tid = threadIdx.x;
    const float* ps = g_sum + bg*NTILES;
    const float* pq = g_sq  + bg*NTILES;
    float s1 = ps[tid] + ps[tid+256];
    float s2 = pq[tid] + pq[tid+256];
    sh1[tid] = s1; sh2[tid] = s2;
    __syncthreads();
    for (int off = 128; off; off >>= 1) {
        if (tid < off) { sh1[tid] += sh1[tid+off]; sh2[tid] += sh2[tid+off]; }
        __syncthreads();
    }
    if (tid == 0) {
        const float cnt = (float)(GSIZE*NVOX);     // 524288
        float mean = sh1[0] / cnt;
        float var  = sh2[0] / cnt - mean*mean;
        g_stats[bg] = make_float2(mean, rsqrtf(var + 1e-5f));
    }
}

// ---------------------------------------------------------------------------
// Kernel 3: apply GroupNorm affine in place
// ---------------------------------------------------------------------------
extern "C" __global__ void gn_apply(float* __restrict__ out,
                                    const float* __restrict__ gamma,
                                    const float* __restrict__ beta) {
    size_t idx4 = (size_t)blockIdx.x * blockDim.x + threadIdx.x;   // float4 index
    size_t elem = idx4 * 4;
    int b = (int)(elem >> 22);                 // CC*NVOX = 2^22
    int c = (int)((elem >> 15) & 127);         // NVOX = 2^15
    float2 st = g_stats[b*NGROUPS + (c >> 4)];
    float ga = __ldg(&gamma[c]);
    float be = __ldg(&beta[c]);
    float4 v = *(float4*)(out + elem);
    float sc = st.y * ga;
    v.x = (v.x - st.x)*sc + be;
    v.y = (v.y - st.x)*sc + be;
    v.z = (v.z - st.x)*sc + be;
    v.w = (v.w - st.x)*sc + be;
    *(float4*)(out + elem) = v;
}

// ---------------------------------------------------------------------------
extern "C" void kernel_launch(void* const* d_in, const int* in_sizes, int n_in,
                              void* d_out, int out_size) {
    const float* skip  = (const float*)d_in[0];
    const float* dec   = (const float*)d_in[1];
    const float* wq    = (const float*)d_in[2];
    const float* wk    = (const float*)d_in[3];
    const float* wv    = (const float*)d_in[4];
    const float* bq    = (const float*)d_in[5];
    const float* bk    = (const float*)d_in[6];
    const float* bv    = (const float*)d_in[7];
    const float* wo    = (const float*)d_in[8];
    const float* bo    = (const float*)d_in[9];
    const float* gamma = (const float*)d_in[10];
    const float* beta  = (const float*)d_in[11];
    float* out = (float*)d_out;

    const size_t smem = (size_t)(2*SW + SY + SSP + 4*SHN) * sizeof(float); // 176128 B
    cudaFuncSetAttribute(attn_fused, cudaFuncAttributeMaxDynamicSharedMemorySize, (int)smem);

    transpose_w<<<256, 256>>>(wq, wk, wv, wo);
    dim3 grid(NTILES, NB);
    attn_fused<<<grid, 256, smem>>>(skip, dec, bq, bk, bv, bo, out);
    gn_stats<<<NB*NGROUPS, 256>>>();
    gn_apply<<<(NB*CC*NVOX/4)/256, 256>>>(out, gamma, beta);
}

// round 5
// speedup vs baseline: 1.3915x; 1.3915x over previous
#include <cuda_runtime.h>
#include <cuda_bf16.h>
#include <math.h>
#include <stdint.h>

// ---------------------------------------------------------------------------
// Problem constants
// ---------------------------------------------------------------------------
#define CC      128
#define TN      64
#define NCOND   4
#define NVOX    32768
#define NTILES  512
#define NB      2
#define NGROUPS 8

// smem byte offsets (from 1024-aligned base)
#define OFF_WAH  0          // weight slot A hi (Wq -> Wk -> Wo) 32KB, swizzled [co][k]
#define OFF_WAL  32768      // slot A lo
#define OFF_WBH  65536      // Wv hi
#define OFF_WBL  98304      // Wv lo
#define OFF_YH   131072     // activation tile hi [n=64][k=128] bf16 swizzled (16KB)
#define OFF_YL   147456     // activation tile lo
#define OFF_SP   163840     // scores [8 heads][64 vox] f32
#define OFF_MS   165888     // running max
#define OFF_LS   167936     // running sumexp
#define OFF_CS   169984     // correction
#define OFF_PP   172032     // p = exp(s-m)
#define OFF_STG  65536      // fp32 epilogue staging [128][72] (36864B) overlays Wv
#define STG_STRIDE 72
#define SMEM_REQ (174080 + 1024)

// ---------------------------------------------------------------------------
// global scratch (no allocations allowed)
// ---------------------------------------------------------------------------
__device__ __nv_bfloat16 g_wh[4][CC*CC];   // Wq,Wk,Wv,Wo hi — swizzled [co][k]
__device__ __nv_bfloat16 g_wl[4][CC*CC];   // lo parts
__device__ float  g_sum[NB*NGROUPS*NTILES];
__device__ float  g_sq [NB*NGROUPS*NTILES];
__device__ float2 g_stats[NB*NGROUPS];

// ---------------------------------------------------------------------------
// PTX wrappers (all plain sm_80-era ISA — no 'a'-suffix features)
// ---------------------------------------------------------------------------
__device__ __forceinline__ uint32_t smem_to_u32(const void* p) {
    uint32_t a;
    asm("{ .reg .u64 t; cvta.to.shared.u64 t, %1; cvt.u32.u64 %0, t; }" : "=r"(a) : "l"(p));
    return a;
}
__device__ __forceinline__ void ldsm4(uint32_t r[4], uint32_t addr) {
    asm volatile("ldmatrix.sync.aligned.m8n8.x4.shared.b16 {%0,%1,%2,%3}, [%4];"
                 : "=r"(r[0]), "=r"(r[1]), "=r"(r[2]), "=r"(r[3]) : "r"(addr));
}
__device__ __forceinline__ void mma16816(float d[4], const uint32_t a[4],
                                         uint32_t b0, uint32_t b1) {
    asm volatile("mma.sync.aligned.m16n8k16.row.col.f32.bf16.bf16.f32 "
                 "{%0,%1,%2,%3}, {%4,%5,%6,%7}, {%8,%9}, {%0,%1,%2,%3};"
                 : "+f"(d[0]), "+f"(d[1]), "+f"(d[2]), "+f"(d[3])
                 : "r"(a[0]), "r"(a[1]), "r"(a[2]), "r"(a[3]), "r"(b0), "r"(b1));
}

// swizzled byte offset inside a [rows][128] bf16 tile with 256B rows:
// unit (16B granule) index is XORed with (row & 7) -> conflict-free ldmatrix.
__device__ __forceinline__ uint32_t swz(int row, int k) {
    return (uint32_t)(row * 256 + ((((k >> 3) ^ (row & 7)) & 15) << 4) + (k & 7) * 2);
}

// ---------------------------------------------------------------------------
// one logical GEMM slab, bf16x3: acc[nb][4] += W[16w:16w+16, :] @ Yt[:, :].T
// A = weights (hi/lo, swizzled [co][k]); B = activations (hi/lo, swizzled [n][k]).
// 24 mma + 10 ldmatrix per k-chunk; 8 k-chunks.
// ---------------------------------------------------------------------------
__device__ __forceinline__ void gemm3(float acc[8][4],
                                      uint32_t wah, uint32_t wal,
                                      uint32_t yh, uint32_t yl,
                                      int w, int lane) {
    const int row  = lane & 15;              // ldmatrix row selector
    const int half = lane >> 4;              // k-unit half selector
#pragma unroll
    for (int kc = 0; kc < 8; kc++) {
        const uint32_t uoff = (uint32_t)(((((2*kc + half) ^ (row & 7)) & 15)) << 4);
        uint32_t Ah[4], Al[4];
        ldsm4(Ah, wah + (uint32_t)(16*w + row)*256 + uoff);
        ldsm4(Al, wal + (uint32_t)(16*w + row)*256 + uoff);
#pragma unroll
        for (int nb2 = 0; nb2 < 4; nb2++) {
            uint32_t Bh[4], Bl[4];
            ldsm4(Bh, yh + (uint32_t)(16*nb2 + row)*256 + uoff);
            ldsm4(Bl, yl + (uint32_t)(16*nb2 + row)*256 + uoff);
            mma16816(acc[2*nb2],   Ah, Bh[0], Bh[2]);
            mma16816(acc[2*nb2+1], Ah, Bh[1], Bh[3]);
            mma16816(acc[2*nb2],   Ah, Bl[0], Bl[2]);
            mma16816(acc[2*nb2+1], Ah, Bl[1], Bl[3]);
            mma16816(acc[2*nb2],   Al, Bh[0], Bh[2]);
            mma16816(acc[2*nb2+1], Al, Bh[1], Bh[3]);
        }
    }
}

__device__ __forceinline__ void add_bias_frag(float acc[8][4], const float* __restrict__ bias,
                                              int w, int lane) {
    float b0 = __ldg(&bias[16*w + (lane >> 2)]);
    float b1 = __ldg(&bias[16*w + (lane >> 2) + 8]);
#pragma unroll
    for (int nb = 0; nb < 8; nb++) {
        acc[nb][0] += b0; acc[nb][1] += b0;
        acc[nb][2] += b1; acc[nb][3] += b1;
    }
}

// ---------------------------------------------------------------------------
// Kernel 0: split weights into bf16 hi/lo, pre-swizzled [co][k] (runs once)
// ---------------------------------------------------------------------------
extern "C" __global__ void prep_w(const float* __restrict__ wq, const float* __restrict__ wk,
                                  const float* __restrict__ wv, const float* __restrict__ wo) {
    int idx = blockIdx.x * 256 + threadIdx.x;   // 0..65535
    int m = idx >> 14, e = idx & 16383;
    int co = e >> 7, k = e & 127;
    const float* src = (m == 0) ? wq : (m == 1) ? wk : (m == 2) ? wv : wo;
    float v = src[e];
    __nv_bfloat16 h = __float2bfloat16_rn(v);
    __nv_bfloat16 l = __float2bfloat16_rn(v - __bfloat162float(h));
    uint32_t off = swz(co, k) >> 1;
    g_wh[m][off] = h;
    g_wl[m][off] = l;
}

// ---------------------------------------------------------------------------
// staging helpers
// ---------------------------------------------------------------------------
__device__ __forceinline__ void copy32k(char* dst, const __nv_bfloat16* __restrict__ src, int tid) {
    const float4* s = (const float4*)src;
    float4* d = (float4*)dst;
#pragma unroll
    for (int it = 0; it < 8; it++) d[it*256 + tid] = s[it*256 + tid];
}

// f32 tile [128 ch][64 vox] (row stride NVOX) -> bf16 hi/lo tiles [vox][k] swizzled
__device__ __forceinline__ void stage_tile(char* smb, const float* __restrict__ src, int tid) {
#pragma unroll
    for (int it = 0; it < 16; it++) {
        int idx = it*256 + tid;        // 0..4095
        int vox = idx & 63;
        int k   = (idx >> 6) * 2;      // even channel
        float x0 = src[(size_t)k*NVOX + vox];
        float x1 = src[(size_t)(k+1)*NVOX + vox];
        __nv_bfloat16 h0 = __float2bfloat16_rn(x0);
        __nv_bfloat16 h1 = __float2bfloat16_rn(x1);
        __nv_bfloat16 l0 = __float2bfloat16_rn(x0 - __bfloat162float(h0));
        __nv_bfloat16 l1 = __float2bfloat16_rn(x1 - __bfloat162float(h1));
        uint32_t off = swz(vox, k);
        uint32_t hw = (uint32_t)__bfloat16_as_ushort(h0) | ((uint32_t)__bfloat16_as_ushort(h1) << 16);
        uint32_t lw = (uint32_t)__bfloat16_as_ushort(l0) | ((uint32_t)__bfloat16_as_ushort(l1) << 16);
        *(uint32_t*)(smb + OFF_YH + off) = hw;
        *(uint32_t*)(smb + OFF_YL + off) = lw;
    }
}

// ---------------------------------------------------------------------------
// Kernel 1: fused attention tile via mma.sync (bf16x3).
// 256 thr = 8 warps; warp w owns channel rows [16w, 16w+16) == head w.
// ---------------------------------------------------------------------------
extern "C" __global__ void __launch_bounds__(256, 1)
attn_fused(const float* __restrict__ skip, const float* __restrict__ dec,
           const float* __restrict__ bq, const float* __restrict__ bk,
           const float* __restrict__ bv, const float* __restrict__ bo,
           float* __restrict__ out)
{
    extern __shared__ char smraw[];
    char* smb = (char*)(((uintptr_t)smraw + 1023) & ~(uintptr_t)1023);
    const uint32_t sb = smem_to_u32(smb);

    float* sp = (float*)(smb + OFF_SP);
    float* ms = (float*)(smb + OFF_MS);
    float* ls = (float*)(smb + OFF_LS);
    float* cs = (float*)(smb + OFF_CS);
    float* pp = (float*)(smb + OFF_PP);
    float* stg = (float*)(smb + OFF_STG);

    const int tid = threadIdx.x;
    const int w = tid >> 5, lane = tid & 31;
    const int tile = blockIdx.x, b = blockIdx.y;
    const int j4 = lane & 3;                 // column-pair selector in fragments

    const size_t voxBase = (size_t)tile * TN;
    const float* decb  = dec  + (size_t)b*CC*NVOX + voxBase;
    const float* skipb = skip + (size_t)b*NCOND*CC*NVOX + voxBase;

    // stage Wq (slot A) + X tile; init softmax state
    copy32k(smb + OFF_WAH, g_wh[0], tid);
    copy32k(smb + OFF_WAL, g_wl[0], tid);
    stage_tile(smb, decb, tid);
    ms[tid] = -INFINITY; ms[tid+256] = -INFINITY;
    ls[tid] = 0.0f;      ls[tid+256] = 0.0f;
    __syncthreads();

    // ---- Q projection (fragments kept in registers) ----
    float q[8][4];
#pragma unroll
    for (int nb = 0; nb < 8; nb++)
#pragma unroll
        for (int r = 0; r < 4; r++) q[nb][r] = 0.0f;
    gemm3(q, sb + OFF_WAH, sb + OFF_WAL, sb + OFF_YH, sb + OFF_YL, w, lane);
    add_bias_frag(q, bq, w, lane);

    float oacc[8][4];
#pragma unroll
    for (int nb = 0; nb < 8; nb++)
#pragma unroll
        for (int r = 0; r < 4; r++) oacc[nb][r] = 0.0f;

    __syncthreads();                      // Q done -> slot A reusable
    copy32k(smb + OFF_WAH, g_wh[1], tid); // Wk
    copy32k(smb + OFF_WAL, g_wl[1], tid);
    copy32k(smb + OFF_WBH, g_wh[2], tid); // Wv
    copy32k(smb + OFF_WBL, g_wl[2], tid);

    for (int cd = 0; cd < NCOND; cd++) {
        __syncthreads();                  // Y tile free, weights staged
        stage_tile(smb, skipb + (size_t)cd*CC*NVOX, tid);
        __syncthreads();

        // ---- K projection + scores (head w lives entirely in warp w) ----
        float kf[8][4];
#pragma unroll
        for (int nb = 0; nb < 8; nb++)
#pragma unroll
            for (int r = 0; r < 4; r++) kf[nb][r] = 0.0f;
        gemm3(kf, sb + OFF_WAH, sb + OFF_WAL, sb + OFF_YH, sb + OFF_YL, w, lane);
        add_bias_frag(kf, bk, w, lane);

#pragma unroll
        for (int nb = 0; nb < 8; nb++) {
            float pA = fmaf(q[nb][0], kf[nb][0], q[nb][2]*kf[nb][2]);
            float pB = fmaf(q[nb][1], kf[nb][1], q[nb][3]*kf[nb][3]);
#pragma unroll
            for (int off = 4; off <= 16; off <<= 1) {
                pA += __shfl_xor_sync(0xffffffffu, pA, off);
                pB += __shfl_xor_sync(0xffffffffu, pB, off);
            }
            if (lane < 4) {
                sp[w*TN + 8*nb + 2*lane]     = pA;
                sp[w*TN + 8*nb + 2*lane + 1] = pB;
            }
        }
        __syncthreads();

        // online softmax state update: 512 (head,voxel) items over 256 threads
#pragma unroll
        for (int t = tid; t < 512; t += 256) {
            float s  = sp[t] * 0.25f;                 // 1/sqrt(head_dim=16)
            float mo = ms[t];
            float mn = fmaxf(mo, s);
            float corr = __expf(mo - mn);
            float pv   = __expf(s - mn);
            ls[t] = ls[t]*corr + pv;
            ms[t] = mn;
            cs[t] = corr;
            pp[t] = pv;
        }
        __syncthreads();

        // ---- V projection + PV accumulate ----
        float vf[8][4];
#pragma unroll
        for (int nb = 0; nb < 8; nb++)
#pragma unroll
            for (int r = 0; r < 4; r++) vf[nb][r] = 0.0f;
        gemm3(vf, sb + OFF_WBH, sb + OFF_WBL, sb + OFF_YH, sb + OFF_YL, w, lane);
        add_bias_frag(vf, bv, w, lane);

#pragma unroll
        for (int nb = 0; nb < 8; nb++) {
            int col = 8*nb + 2*j4;
            float c0 = cs[w*TN + col], c1 = cs[w*TN + col + 1];
            float p0 = pp[w*TN + col], p1 = pp[w*TN + col + 1];
            oacc[nb][0] = fmaf(oacc[nb][0], c0, p0*vf[nb][0]);
            oacc[nb][1] = fmaf(oacc[nb][1], c1, p1*vf[nb][1]);
            oacc[nb][2] = fmaf(oacc[nb][2], c0, p0*vf[nb][2]);
            oacc[nb][3] = fmaf(oacc[nb][3], c1, p1*vf[nb][3]);
        }
    }

    // ---- finalize attention output into Y tile (bf16 hi/lo), stage Wo ----
    __syncthreads();                      // all V GEMMs done reading Y tile
    {
        const int r0 = 16*w + (lane >> 2);
#pragma unroll
        for (int nb = 0; nb < 8; nb++) {
            int col = 8*nb + 2*j4;
            float inv0 = 1.0f / ls[w*TN + col];
            float inv1 = 1.0f / ls[w*TN + col + 1];
            float o00 = oacc[nb][0] * inv0;
            float o01 = oacc[nb][1] * inv1;
            float o10 = oacc[nb][2] * inv0;
            float o11 = oacc[nb][3] * inv1;
#pragma unroll
            for (int e = 0; e < 4; e++) {
                float ov = (e == 0) ? o00 : (e == 1) ? o01 : (e == 2) ? o10 : o11;
                int rr = r0 + ((e >> 1) ? 8 : 0);
                int cc = col + (e & 1);
                __nv_bfloat16 h = __float2bfloat16_rn(ov);
                __nv_bfloat16 l = __float2bfloat16_rn(ov - __bfloat162float(h));
                uint32_t off = swz(cc, rr);          // Y tile is [n][k=channel]
                *(__nv_bfloat16*)(smb + OFF_YH + off) = h;
                *(__nv_bfloat16*)(smb + OFF_YL + off) = l;
            }
        }
    }
    copy32k(smb + OFF_WAH, g_wh[3], tid);  // Wo into slot A
    copy32k(smb + OFF_WAL, g_wl[3], tid);
    __syncthreads();

    // ---- O projection ----
    float of[8][4];
#pragma unroll
    for (int nb = 0; nb < 8; nb++)
#pragma unroll
        for (int r = 0; r < 4; r++) of[nb][r] = 0.0f;
    gemm3(of, sb + OFF_WAH, sb + OFF_WAL, sb + OFF_YH, sb + OFF_YL, w, lane);

    // stage O fragments to fp32 smem [128][72] (overlays dead Wv slot)
    {
        const int r0 = 16*w + (lane >> 2);
#pragma unroll
        for (int nb = 0; nb < 8; nb++) {
            int col = 8*nb + 2*j4;
            *(float2*)&stg[ r0      * STG_STRIDE + col] = make_float2(of[nb][0], of[nb][1]);
            *(float2*)&stg[(r0 + 8) * STG_STRIDE + col] = make_float2(of[nb][2], of[nb][3]);
        }
    }
    __syncthreads();

    // ---- epilogue: bias + residual + store + GN partials (R2 mapping) ----
    const int cy = tid >> 4, nx = tid & 15;
    const int co0 = cy*8, n0 = nx*4;
    float* outb = out + (size_t)b*CC*NVOX + voxBase;
    float s1 = 0.0f, s2 = 0.0f;
#pragma unroll
    for (int i = 0; i < 8; i++) {
        int co = co0 + i;
        float boc = __ldg(&bo[co]);
        float4 rv = *(const float4*)(decb + (size_t)co*NVOX + n0);
        float4 ov = *(const float4*)&stg[co*STG_STRIDE + n0];
        float u0 = ov.x + boc + rv.x;
        float u1 = ov.y + boc + rv.y;
        float u2 = ov.z + boc + rv.z;
        float u3 = ov.w + boc + rv.w;
        *(float4*)(outb + (size_t)co*NVOX + n0) = make_float4(u0, u1, u2, u3);
        s1 += (u0 + u1) + (u2 + u3);
        s2 += fmaf(u0, u0, u1*u1) + fmaf(u2, u2, u3*u3);
    }
#pragma unroll
    for (int off = 16; off; off >>= 1) {
        s1 += __shfl_xor_sync(0xffffffffu, s1, off);
        s2 += __shfl_xor_sync(0xffffffffu, s2, off);
    }
    if (lane == 0) {
        int slot = (b*NGROUPS + w)*NTILES + tile;   // warp w's 32 channels = GN group w
        g_sum[slot] = s1;
        g_sq[slot]  = s2;
    }
}

// ---------------------------------------------------------------------------
// Kernel 2: reduce per-tile partials into per-(batch,group) mean / rstd
// ---------------------------------------------------------------------------
extern "C" __global__ void gn_stats() {
    __shared__ float sh1[256], sh2[256];
    const int bg = blockIdx.x;        // 0..15
    const int tid = threadIdx.x;
    const float* ps = g_sum + bg*NTILES;
    const float* pq = g_sq  + bg*NTILES;
    float s1 = ps[tid] + ps[tid+256];
    float s2 = pq[tid] + pq[tid+256];
    sh1[tid] = s1; sh2[tid] = s2;
    __syncthreads();
    for (int off = 128; off; off >>= 1) {
        if (tid < off) { sh1[tid] += sh1[tid+off]; sh2[tid] += sh2[tid+off]; }
        __syncthreads();
    }
    if (tid == 0) {
        const float cnt = (float)(16 * NVOX);      // 524288
        float mean = sh1[0] / cnt;
        float var  = sh2[0] / cnt - mean*mean;
        g_stats[bg] = make_float2(mean, rsqrtf(var + 1e-5f));
    }
}

// ---------------------------------------------------------------------------
// Kernel 3: apply GroupNorm affine in place
// ---------------------------------------------------------------------------
extern "C" __global__ void gn_apply(float* __restrict__ out,
                                    const float* __restrict__ gamma,
                                    const float* __restrict__ beta) {
    size_t elem = ((size_t)blockIdx.x * blockDim.x + threadIdx.x) * 4;
    int b = (int)(elem >> 22);
    int c = (int)((elem >> 15) & 127);
    float2 st = g_stats[b*NGROUPS + (c >> 4)];
    float ga = __ldg(&gamma[c]), be = __ldg(&beta[c]);
    float4 v = *(float4*)(out + elem);
    float sc = st.y * ga;
    v.x = (v.x - st.x)*sc + be;
    v.y = (v.y - st.x)*sc + be;
    v.z = (v.z - st.x)*sc + be;
    v.w = (v.w - st.x)*sc + be;
    *(float4*)(out + elem) = v;
}

// ---------------------------------------------------------------------------
extern "C" void kernel_launch(void* const* d_in, const int* in_sizes, int n_in,
                              void* d_out, int out_size) {
    const float* skip  = (const float*)d_in[0];
    const float* dec   = (const float*)d_in[1];
    const float* wq    = (const float*)d_in[2];
    const float* wk    = (const float*)d_in[3];
    const float* wv    = (const float*)d_in[4];
    const float* bq    = (const float*)d_in[5];
    const float* bk    = (const float*)d_in[6];
    const float* bv    = (const float*)d_in[7];
    const float* wo    = (const float*)d_in[8];
    const float* bo    = (const float*)d_in[9];
    const float* gamma = (const float*)d_in[10];
    const float* beta  = (const float*)d_in[11];
    float* out = (float*)d_out;

    cudaFuncSetAttribute(attn_fused, cudaFuncAttributeMaxDynamicSharedMemorySize, SMEM_REQ);

    prep_w<<<256, 256>>>(wq, wk, wv, wo);
    dim3 grid(NTILES, NB);
    attn_fused<<<grid, 256, SMEM_REQ>>>(skip, dec, bq, bk, bv, bo, out);
    gn_stats<<<NB*NGROUPS, 256>>>();
    gn_apply<<<(NB*CC*NVOX/4)/256, 256>>>(out, gamma, beta);
}

// round 6
// speedup vs baseline: 1.6640x; 1.1959x over previous
#include <cuda_runtime.h>
#include <cuda_fp16.h>
#include <math.h>
#include <stdint.h>

// ---------------------------------------------------------------------------
// Problem constants
// ---------------------------------------------------------------------------
#define CC      128
#define TN      64
#define NCOND   4
#define NVOX    32768
#define NTILES  512
#define NB      2
#define NGROUPS 8

// smem byte offsets (from 1024-aligned base)
#define OFF_WAH  0          // slot A hi (Wq -> Wk -> Wo) 32KB fp16 swizzled [co][k]
#define OFF_WAL  32768      // slot A lo
#define OFF_WBH  65536      // Wv hi
#define OFF_WBL  98304      // Wv lo
#define OFF_Y    131072     // activation tile [n=64][k=128] fp16 swizzled (16KB)
#define OFF_SP   147456     // scores [8 heads][64 vox] f32
#define OFF_MS   149504     // running max
#define OFF_LS   151552     // running sumexp
#define OFF_CS   153600     // correction
#define OFF_PP   155648     // p = exp(s-m)
#define OFF_STG  65536      // fp32 epilogue staging [128][72] overlays Wv (36864B)
#define STG_STRIDE 72
#define SMEM_REQ (157696 + 1024)

// ---------------------------------------------------------------------------
// global scratch (no allocations allowed)
// ---------------------------------------------------------------------------
__device__ __half g_wh[4][CC*CC];   // Wq,Wk,Wv,Wo hi — swizzled [co][k]
__device__ __half g_wl[4][CC*CC];   // lo parts (w = wh + wl, ~exact)
__device__ float  g_sum[NB*NGROUPS*NTILES];
__device__ float  g_sq [NB*NGROUPS*NTILES];
__device__ float2 g_stats[NB*NGROUPS];

// ---------------------------------------------------------------------------
// PTX wrappers (plain sm_80-era ISA — no 'a'-suffix features)
// ---------------------------------------------------------------------------
__device__ __forceinline__ uint32_t smem_to_u32(const void* p) {
    uint32_t a;
    asm("{ .reg .u64 t; cvta.to.shared.u64 t, %1; cvt.u32.u64 %0, t; }" : "=r"(a) : "l"(p));
    return a;
}
__device__ __forceinline__ void ldsm4(uint32_t r[4], uint32_t addr) {
    asm volatile("ldmatrix.sync.aligned.m8n8.x4.shared.b16 {%0,%1,%2,%3}, [%4];"
                 : "=r"(r[0]), "=r"(r[1]), "=r"(r[2]), "=r"(r[3]) : "r"(addr));
}
__device__ __forceinline__ void mma16816(float d[4], const uint32_t a[4],
                                         uint32_t b0, uint32_t b1) {
    asm volatile("mma.sync.aligned.m16n8k16.row.col.f32.f16.f16.f32 "
                 "{%0,%1,%2,%3}, {%4,%5,%6,%7}, {%8,%9}, {%0,%1,%2,%3};"
                 : "+f"(d[0]), "+f"(d[1]), "+f"(d[2]), "+f"(d[3])
                 : "r"(a[0]), "r"(a[1]), "r"(a[2]), "r"(a[3]), "r"(b0), "r"(b1));
}

// swizzled byte offset inside a [rows][128] fp16 tile with 256B rows:
// 16B-unit index XORed with (row & 7) -> conflict-free ldmatrix.
__device__ __forceinline__ uint32_t swz(int row, int k) {
    return (uint32_t)(row * 256 + ((((k >> 3) ^ (row & 7)) & 15) << 4) + (k & 7) * 2);
}

// ---------------------------------------------------------------------------
// GEMM (fp16x2): acc[nb][4] += (Wh+Wl)[16w:16w+16, :] @ Y[:, :].T
// A hi/lo fp16 swizzled [co][k]; B single fp16 swizzled [n][k].
// ---------------------------------------------------------------------------
__device__ __forceinline__ void gemm2(float acc[8][4],
                                      uint32_t wah, uint32_t wal, uint32_t y,
                                      int w, int lane) {
    const int row  = lane & 15;
    const int half = lane >> 4;
#pragma unroll
    for (int kc = 0; kc < 8; kc++) {
        const uint32_t uoff = (uint32_t)((((2*kc + half) ^ (row & 7)) & 15) << 4);
        uint32_t Ah[4], Al[4];
        ldsm4(Ah, wah + (uint32_t)(16*w + row)*256 + uoff);
        ldsm4(Al, wal + (uint32_t)(16*w + row)*256 + uoff);
#pragma unroll
        for (int nb2 = 0; nb2 < 4; nb2++) {
            uint32_t B[4];
            ldsm4(B, y + (uint32_t)(16*nb2 + row)*256 + uoff);
            mma16816(acc[2*nb2],   Ah, B[0], B[2]);
            mma16816(acc[2*nb2+1], Ah, B[1], B[3]);
            mma16816(acc[2*nb2],   Al, B[0], B[2]);
            mma16816(acc[2*nb2+1], Al, B[1], B[3]);
        }
    }
}

// fused K+V GEMM: B fragments loaded once, feed both accumulators
__device__ __forceinline__ void gemm2_kv(float kf[8][4], float vf[8][4],
                                         uint32_t kah, uint32_t kal,
                                         uint32_t vah, uint32_t val_,
                                         uint32_t y, int w, int lane) {
    const int row  = lane & 15;
    const int half = lane >> 4;
#pragma unroll
    for (int kc = 0; kc < 8; kc++) {
        const uint32_t uoff = (uint32_t)((((2*kc + half) ^ (row & 7)) & 15) << 4);
        const uint32_t arow = (uint32_t)(16*w + row)*256 + uoff;
        uint32_t KAh[4], KAl[4], VAh[4], VAl[4];
        ldsm4(KAh, kah + arow);
        ldsm4(KAl, kal + arow);
        ldsm4(VAh, vah + arow);
        ldsm4(VAl, val_ + arow);
#pragma unroll
        for (int nb2 = 0; nb2 < 4; nb2++) {
            uint32_t B[4];
            ldsm4(B, y + (uint32_t)(16*nb2 + row)*256 + uoff);
            mma16816(kf[2*nb2],   KAh, B[0], B[2]);
            mma16816(kf[2*nb2+1], KAh, B[1], B[3]);
            mma16816(kf[2*nb2],   KAl, B[0], B[2]);
            mma16816(kf[2*nb2+1], KAl, B[1], B[3]);
            mma16816(vf[2*nb2],   VAh, B[0], B[2]);
            mma16816(vf[2*nb2+1], VAh, B[1], B[3]);
            mma16816(vf[2*nb2],   VAl, B[0], B[2]);
            mma16816(vf[2*nb2+1], VAl, B[1], B[3]);
        }
    }
}

__device__ __forceinline__ void add_bias_frag(float acc[8][4], const float* __restrict__ bias,
                                              int w, int lane) {
    float b0 = __ldg(&bias[16*w + (lane >> 2)]);
    float b1 = __ldg(&bias[16*w + (lane >> 2) + 8]);
#pragma unroll
    for (int nb = 0; nb < 8; nb++) {
        acc[nb][0] += b0; acc[nb][1] += b0;
        acc[nb][2] += b1; acc[nb][3] += b1;
    }
}

// ---------------------------------------------------------------------------
// Kernel 0: split weights into fp16 hi/lo, pre-swizzled [co][k] (runs once)
// ---------------------------------------------------------------------------
extern "C" __global__ void prep_w(const float* __restrict__ wq, const float* __restrict__ wk,
                                  const float* __restrict__ wv, const float* __restrict__ wo) {
    int idx = blockIdx.x * 256 + threadIdx.x;   // 0..65535
    int m = idx >> 14, e = idx & 16383;
    int co = e >> 7, k = e & 127;
    const float* src = (m == 0) ? wq : (m == 1) ? wk : (m == 2) ? wv : wo;
    float v = src[e];
    __half h = __float2half_rn(v);
    __half l = __float2half_rn(v - __half2float(h));
    uint32_t off = swz(co, k) >> 1;
    g_wh[m][off] = h;
    g_wl[m][off] = l;
}

// ---------------------------------------------------------------------------
// staging helpers
// ---------------------------------------------------------------------------
__device__ __forceinline__ void copy32k(char* dst, const __half* __restrict__ src, int tid) {
    const float4* s = (const float4*)src;
    float4* d = (float4*)dst;
#pragma unroll
    for (int it = 0; it < 8; it++) d[it*256 + tid] = s[it*256 + tid];
}

// f32 tile [128 ch][64 vox] (row stride NVOX) -> single fp16 tile [vox][k] swizzled
__device__ __forceinline__ void stage_tile(char* smb, const float* __restrict__ src, int tid) {
#pragma unroll
    for (int it = 0; it < 16; it++) {
        int idx = it*256 + tid;        // 0..4095
        int vox = idx & 63;
        int k   = (idx >> 6) * 2;      // even channel
        float x0 = src[(size_t)k*NVOX + vox];
        float x1 = src[(size_t)(k+1)*NVOX + vox];
        __half h0 = __float2half_rn(x0);
        __half h1 = __float2half_rn(x1);
        uint32_t hw = (uint32_t)__half_as_ushort(h0) | ((uint32_t)__half_as_ushort(h1) << 16);
        *(uint32_t*)(smb + OFF_Y + swz(vox, k)) = hw;
    }
}

// ---------------------------------------------------------------------------
// Kernel 1: fused attention tile via mma.sync (fp16x2, fused K+V).
// 256 thr = 8 warps; warp w owns channel rows [16w, 16w+16) == head w.
// ---------------------------------------------------------------------------
extern "C" __global__ void __launch_bounds__(256, 1)
attn_fused(const float* __restrict__ skip, const float* __restrict__ dec,
           const float* __restrict__ bq, const float* __restrict__ bk,
           const float* __restrict__ bv, const float* __restrict__ bo,
           float* __restrict__ out)
{
    extern __shared__ char smraw[];
    char* smb = (char*)(((uintptr_t)smraw + 1023) & ~(uintptr_t)1023);
    const uint32_t sb = smem_to_u32(smb);

    float* sp = (float*)(smb + OFF_SP);
    float* ms = (float*)(smb + OFF_MS);
    float* ls = (float*)(smb + OFF_LS);
    float* cs = (float*)(smb + OFF_CS);
    float* pp = (float*)(smb + OFF_PP);
    float* stg = (float*)(smb + OFF_STG);

    const int tid = threadIdx.x;
    const int w = tid >> 5, lane = tid & 31;
    const int tile = blockIdx.x, b = blockIdx.y;
    const int j4 = lane & 3;

    const size_t voxBase = (size_t)tile * TN;
    const float* decb  = dec  + (size_t)b*CC*NVOX + voxBase;
    const float* skipb = skip + (size_t)b*NCOND*CC*NVOX + voxBase;

    // stage Wq (slot A) + X tile; init softmax state
    copy32k(smb + OFF_WAH, g_wh[0], tid);
    copy32k(smb + OFF_WAL, g_wl[0], tid);
    stage_tile(smb, decb, tid);
    ms[tid] = -INFINITY; ms[tid+256] = -INFINITY;
    ls[tid] = 0.0f;      ls[tid+256] = 0.0f;
    __syncthreads();

    // ---- Q projection ----
    float q[8][4];
#pragma unroll
    for (int nb = 0; nb < 8; nb++)
#pragma unroll
        for (int r = 0; r < 4; r++) q[nb][r] = 0.0f;
    gemm2(q, sb + OFF_WAH, sb + OFF_WAL, sb + OFF_Y, w, lane);
    add_bias_frag(q, bq, w, lane);

    float oacc[8][4];
#pragma unroll
    for (int nb = 0; nb < 8; nb++)
#pragma unroll
        for (int r = 0; r < 4; r++) oacc[nb][r] = 0.0f;

    __syncthreads();                      // Q done -> slot A reusable
    copy32k(smb + OFF_WAH, g_wh[1], tid); // Wk
    copy32k(smb + OFF_WAL, g_wl[1], tid);
    copy32k(smb + OFF_WBH, g_wh[2], tid); // Wv
    copy32k(smb + OFF_WBL, g_wl[2], tid);

    for (int cd = 0; cd < NCOND; cd++) {
        __syncthreads();                  // Y free, weights staged, cs/pp consumed
        stage_tile(smb, skipb + (size_t)cd*CC*NVOX, tid);
        __syncthreads();

        // ---- fused K+V projection ----
        float kf[8][4], vf[8][4];
#pragma unroll
        for (int nb = 0; nb < 8; nb++)
#pragma unroll
            for (int r = 0; r < 4; r++) { kf[nb][r] = 0.0f; vf[nb][r] = 0.0f; }
        gemm2_kv(kf, vf, sb + OFF_WAH, sb + OFF_WAL, sb + OFF_WBH, sb + OFF_WBL,
                 sb + OFF_Y, w, lane);
        add_bias_frag(kf, bk, w, lane);
        add_bias_frag(vf, bv, w, lane);

        // ---- scores (head w lives entirely in warp w) ----
#pragma unroll
        for (int nb = 0; nb < 8; nb++) {
            float pA = fmaf(q[nb][0], kf[nb][0], q[nb][2]*kf[nb][2]);
            float pB = fmaf(q[nb][1], kf[nb][1], q[nb][3]*kf[nb][3]);
#pragma unroll
            for (int off = 4; off <= 16; off <<= 1) {
                pA += __shfl_xor_sync(0xffffffffu, pA, off);
                pB += __shfl_xor_sync(0xffffffffu, pB, off);
            }
            if (lane < 4) {
                sp[w*TN + 8*nb + 2*lane]     = pA;
                sp[w*TN + 8*nb + 2*lane + 1] = pB;
            }
        }
        __syncthreads();

        // online softmax state: 512 (head,voxel) items over 256 threads
#pragma unroll
        for (int t = tid; t < 512; t += 256) {
            float s  = sp[t] * 0.25f;                 // 1/sqrt(head_dim=16)
            float mo = ms[t];
            float mn = fmaxf(mo, s);
            float corr = __expf(mo - mn);
            float pv   = __expf(s - mn);
            ls[t] = ls[t]*corr + pv;
            ms[t] = mn;
            cs[t] = corr;
            pp[t] = pv;
        }
        __syncthreads();

        // ---- PV accumulate (registers only) ----
#pragma unroll
        for (int nb = 0; nb < 8; nb++) {
            int col = 8*nb + 2*j4;
            float c0 = cs[w*TN + col], c1 = cs[w*TN + col + 1];
            float p0 = pp[w*TN + col], p1 = pp[w*TN + col + 1];
            oacc[nb][0] = fmaf(oacc[nb][0], c0, p0*vf[nb][0]);
            oacc[nb][1] = fmaf(oacc[nb][1], c1, p1*vf[nb][1]);
            oacc[nb][2] = fmaf(oacc[nb][2], c0, p0*vf[nb][2]);
            oacc[nb][3] = fmaf(oacc[nb][3], c1, p1*vf[nb][3]);
        }
    }

    // ---- finalize attention output into Y tile (single fp16), stage Wo ----
    __syncthreads();
    {
        const int r0 = 16*w + (lane >> 2);
#pragma unroll
        for (int nb = 0; nb < 8; nb++) {
            int col = 8*nb + 2*j4;
            float inv0 = 1.0f / ls[w*TN + col];
            float inv1 = 1.0f / ls[w*TN + col + 1];
            float o00 = oacc[nb][0] * inv0;
            float o01 = oacc[nb][1] * inv1;
            float o10 = oacc[nb][2] * inv0;
            float o11 = oacc[nb][3] * inv1;
#pragma unroll
            for (int e = 0; e < 4; e++) {
                float ov = (e == 0) ? o00 : (e == 1) ? o01 : (e == 2) ? o10 : o11;
                int rr = r0 + ((e >> 1) ? 8 : 0);
                int cc = col + (e & 1);
                *(__half*)(smb + OFF_Y + swz(cc, rr)) = __float2half_rn(ov);
            }
        }
    }
    copy32k(smb + OFF_WAH, g_wh[3], tid);  // Wo into slot A
    copy32k(smb + OFF_WAL, g_wl[3], tid);
    __syncthreads();

    // ---- O projection ----
    float of[8][4];
#pragma unroll
    for (int nb = 0; nb < 8; nb++)
#pragma unroll
        for (int r = 0; r < 4; r++) of[nb][r] = 0.0f;
    gemm2(of, sb + OFF_WAH, sb + OFF_WAL, sb + OFF_Y, w, lane);

    // stage O fragments to fp32 smem [128][72] (overlays dead Wv slot)
    {
        const int r0 = 16*w + (lane >> 2);
#pragma unroll
        for (int nb = 0; nb < 8; nb++) {
            int col = 8*nb + 2*j4;
            *(float2*)&stg[ r0      * STG_STRIDE + col] = make_float2(of[nb][0], of[nb][1]);
            *(float2*)&stg[(r0 + 8) * STG_STRIDE + col] = make_float2(of[nb][2], of[nb][3]);
        }
    }
    __syncthreads();

    // ---- epilogue: bias + residual + store + GN partials ----
    const int cy = tid >> 4, nx = tid & 15;
    const int co0 = cy*8, n0 = nx*4;
    float* outb = out + (size_t)b*CC*NVOX + voxBase;
    float s1 = 0.0f, s2 = 0.0f;
#pragma unroll
    for (int i = 0; i < 8; i++) {
        int co = co0 + i;
        float boc = __ldg(&bo[co]);
        float4 rv = *(const float4*)(decb + (size_t)co*NVOX + n0);
        float4 ov = *(const float4*)&stg[co*STG_STRIDE + n0];
        float u0 = ov.x + boc + rv.x;
        float u1 = ov.y + boc + rv.y;
        float u2 = ov.z + boc + rv.z;
        float u3 = ov.w + boc + rv.w;
        *(float4*)(outb + (size_t)co*NVOX + n0) = make_float4(u0, u1, u2, u3);
        s1 += (u0 + u1) + (u2 + u3);
        s2 += fmaf(u0, u0, u1*u1) + fmaf(u2, u2, u3*u3);
    }
#pragma unroll
    for (int off = 16; off; off >>= 1) {
        s1 += __shfl_xor_sync(0xffffffffu, s1, off);
        s2 += __shfl_xor_sync(0xffffffffu, s2, off);
    }
    if (lane == 0) {
        int slot = (b*NGROUPS + w)*NTILES + tile;   // warp w's 32 channels = GN group w
        g_sum[slot] = s1;
        g_sq[slot]  = s2;
    }
}

// ---------------------------------------------------------------------------
// Kernel 2: reduce per-tile partials into per-(batch,group) mean / rstd
// ---------------------------------------------------------------------------
extern "C" __global__ void gn_stats() {
    __shared__ float sh1[256], sh2[256];
    const int bg = blockIdx.x;        // 0..15
    const int tid = threadIdx.x;
    const float* ps = g_sum + bg*NTILES;
    const float* pq = g_sq  + bg*NTILES;
    float s1 = ps[tid] + ps[tid+256];
    float s2 = pq[tid] + pq[tid+256];
    sh1[tid] = s1; sh2[tid] = s2;
    __syncthreads();
    for (int off = 128; off; off >>= 1) {
        if (tid < off) { sh1[tid] += sh1[tid+off]; sh2[tid] += sh2[tid+off]; }
        __syncthreads();
    }
    if (tid == 0) {
        const float cnt = (float)(16 * NVOX);      // 524288
        float mean = sh1[0] / cnt;
        float var  = sh2[0] / cnt - mean*mean;
        g_stats[bg] = make_float2(mean, rsqrtf(var + 1e-5f));
    }
}

// ---------------------------------------------------------------------------
// Kernel 3: apply GroupNorm affine in place (2 float4 per thread)
// ---------------------------------------------------------------------------
extern "C" __global__ void gn_apply(float* __restrict__ out,
                                    const float* __restrict__ gamma,
                                    const float* __restrict__ beta) {
    size_t base4 = (size_t)blockIdx.x * blockDim.x + threadIdx.x;
#pragma unroll
    for (int rep = 0; rep < 2; rep++) {
        size_t elem = (base4 + (size_t)rep * 4096 * 256) * 4;
        int b = (int)(elem >> 22);
        int c = (int)((elem >> 15) & 127);
        float2 st = g_stats[b*NGROUPS + (c >> 4)];
        float ga = __ldg(&gamma[c]), be = __ldg(&beta[c]);
        float4 v = *(float4*)(out + elem);
        float sc = st.y * ga;
        v.x = (v.x - st.x)*sc + be;
        v.y = (v.y - st.x)*sc + be;
        v.z = (v.z - st.x)*sc + be;
        v.w = (v.w - st.x)*sc + be;
        *(float4*)(out + elem) = v;
    }
}

// ---------------------------------------------------------------------------
extern "C" void kernel_launch(void* const* d_in, const int* in_sizes, int n_in,
                              void* d_out, int out_size) {
    const float* skip  = (const float*)d_in[0];
    const float* dec   = (const float*)d_in[1];
    const float* wq    = (const float*)d_in[2];
    const float* wk    = (const float*)d_in[3];
    const float* wv    = (const float*)d_in[4];
    const float* bq    = (const float*)d_in[5];
    const float* bk    = (const float*)d_in[6];
    const float* bv    = (const float*)d_in[7];
    const float* wo    = (const float*)d_in[8];
    const float* bo    = (const float*)d_in[9];
    const float* gamma = (const float*)d_in[10];
    const float* beta  = (const float*)d_in[11];
    float* out = (float*)d_out;

    cudaFuncSetAttribute(attn_fused, cudaFuncAttributeMaxDynamicSharedMemorySize, SMEM_REQ);

    prep_w<<<256, 256>>>(wq, wk, wv, wo);
    dim3 grid(NTILES, NB);
    attn_fused<<<grid, 256, SMEM_REQ>>>(skip, dec, bq, bk, bv, bo, out);
    gn_stats<<<NB*NGROUPS, 256>>>();
    gn_apply<<<4096, 256>>>(out, gamma, beta);
}

// round 9
// speedup vs baseline: 2.4868x; 1.4945x over previous
#include <cuda_runtime.h>
#include <cuda_fp16.h>
#include <math.h>
#include <stdint.h>

// ---------------------------------------------------------------------------
// Problem constants
// ---------------------------------------------------------------------------
#define CC      128
#define TN      64
#define NCOND   4
#define NVOX    32768
#define NTILES  512
#define NB      2
#define NGROUPS 8

// smem byte offsets (from 1024-aligned base).
// NOTE: one fp16 weight matrix = 128 rows x 256 B = 32768 B (NOT 16KB — the
// R7/R8 bug). All weight regions are 32KB.
#define OFF_WA   0          // weight slot A (Wq -> Wo) 32KB fp16 swizzled [co][k]
#define OFF_WK   32768      // Wk 32KB
#define OFF_WV   65536      // Wv 32KB
#define OFF_Y0   98304      // activation buffer 0 [n=64][k=128] fp16 swizzled (16KB)
#define OFF_Y1   114688     // activation buffer 1 (16KB)
#define OFF_SP   131072     // scores [8 heads][64 vox] f32 (2KB)
#define OFF_MS   133120     // running max
#define OFF_LS   135168     // running sumexp
#define OFF_CS   137216     // correction
#define OFF_PP   139264     // p = exp(s-m)
#define OFF_STG  141312     // fp32 epilogue staging [128][72] (36864B)
#define STG_STRIDE 72
#define SMEM_REQ (178176 + 1024)

// ---------------------------------------------------------------------------
// global scratch (no allocations allowed)
// ---------------------------------------------------------------------------
__device__ __half g_w[4][CC*CC];    // Wq,Wk,Wv,Wo fp16 — swizzled [co][k]
__device__ float  g_sum[NB*NGROUPS*NTILES];
__device__ float  g_sq [NB*NGROUPS*NTILES];
__device__ float2 g_stats[NB*NGROUPS];

// ---------------------------------------------------------------------------
// PTX wrappers (plain sm_80-era ISA)
// ---------------------------------------------------------------------------
__device__ __forceinline__ uint32_t smem_to_u32(const void* p) {
    uint32_t a;
    asm("{ .reg .u64 t; cvta.to.shared.u64 t, %1; cvt.u32.u64 %0, t; }" : "=r"(a) : "l"(p));
    return a;
}
__device__ __forceinline__ void ldsm4(uint32_t r[4], uint32_t addr) {
    asm volatile("ldmatrix.sync.aligned.m8n8.x4.shared.b16 {%0,%1,%2,%3}, [%4];"
                 : "=r"(r[0]), "=r"(r[1]), "=r"(r[2]), "=r"(r[3]) : "r"(addr));
}
__device__ __forceinline__ void mma16816(float d[4], const uint32_t a[4],
                                         uint32_t b0, uint32_t b1) {
    asm volatile("mma.sync.aligned.m16n8k16.row.col.f32.f16.f16.f32 "
                 "{%0,%1,%2,%3}, {%4,%5,%6,%7}, {%8,%9}, {%0,%1,%2,%3};"
                 : "+f"(d[0]), "+f"(d[1]), "+f"(d[2]), "+f"(d[3])
                 : "r"(a[0]), "r"(a[1]), "r"(a[2]), "r"(a[3]), "r"(b0), "r"(b1));
}

// swizzled byte offset inside a [rows][128] fp16 tile with 256B rows
__device__ __forceinline__ uint32_t swz(int row, int k) {
    return (uint32_t)(row * 256 + ((((k >> 3) ^ (row & 7)) & 15) << 4) + (k & 7) * 2);
}

// ---------------------------------------------------------------------------
// single-pass fp16 GEMM: acc[nb][4] += W[16w:16w+16, :] @ Y[:, :].T
// ---------------------------------------------------------------------------
__device__ __forceinline__ void gemm1(float acc[8][4], uint32_t wa, uint32_t y,
                                      int w, int lane) {
    const int row  = lane & 15;
    const int half = lane >> 4;
#pragma unroll
    for (int kc = 0; kc < 8; kc++) {
        const uint32_t uoff = (uint32_t)((((2*kc + half) ^ (row & 7)) & 15) << 4);
        uint32_t A[4];
        ldsm4(A, wa + (uint32_t)(16*w + row)*256 + uoff);
#pragma unroll
        for (int nb2 = 0; nb2 < 4; nb2++) {
            uint32_t B[4];
            ldsm4(B, y + (uint32_t)(16*nb2 + row)*256 + uoff);
            mma16816(acc[2*nb2],   A, B[0], B[2]);
            mma16816(acc[2*nb2+1], A, B[1], B[3]);
        }
    }
}

// fused K+V GEMM: B fragments loaded once
__device__ __forceinline__ void gemm1_kv(float kf[8][4], float vf[8][4],
                                         uint32_t wk_, uint32_t wv_, uint32_t y,
                                         int w, int lane) {
    const int row  = lane & 15;
    const int half = lane >> 4;
#pragma unroll
    for (int kc = 0; kc < 8; kc++) {
        const uint32_t uoff = (uint32_t)((((2*kc + half) ^ (row & 7)) & 15) << 4);
        const uint32_t arow = (uint32_t)(16*w + row)*256 + uoff;
        uint32_t KA[4], VA[4];
        ldsm4(KA, wk_ + arow);
        ldsm4(VA, wv_ + arow);
#pragma unroll
        for (int nb2 = 0; nb2 < 4; nb2++) {
            uint32_t B[4];
            ldsm4(B, y + (uint32_t)(16*nb2 + row)*256 + uoff);
            mma16816(kf[2*nb2],   KA, B[0], B[2]);
            mma16816(kf[2*nb2+1], KA, B[1], B[3]);
            mma16816(vf[2*nb2],   VA, B[0], B[2]);
            mma16816(vf[2*nb2+1], VA, B[1], B[3]);
        }
    }
}

__device__ __forceinline__ void add_bias_frag(float acc[8][4], const float* __restrict__ bias,
                                              int w, int lane) {
    float b0 = __ldg(&bias[16*w + (lane >> 2)]);
    float b1 = __ldg(&bias[16*w + (lane >> 2) + 8]);
#pragma unroll
    for (int nb = 0; nb < 8; nb++) {
        acc[nb][0] += b0; acc[nb][1] += b0;
        acc[nb][2] += b1; acc[nb][3] += b1;
    }
}

// ---------------------------------------------------------------------------
// Kernel 0: weights -> fp16, pre-swizzled [co][k] (runs once)
// ---------------------------------------------------------------------------
extern "C" __global__ void prep_w(const float* __restrict__ wq, const float* __restrict__ wk,
                                  const float* __restrict__ wv, const float* __restrict__ wo) {
    int idx = blockIdx.x * 256 + threadIdx.x;   // 0..65535
    int m = idx >> 14, e = idx & 16383;
    int co = e >> 7, k = e & 127;
    const float* src = (m == 0) ? wq : (m == 1) ? wk : (m == 2) ? wv : wo;
    g_w[m][swz(co, k) >> 1] = __float2half_rn(src[e]);
}

// ---------------------------------------------------------------------------
// staging helpers
// ---------------------------------------------------------------------------
// copy one full 32KB weight matrix (2048 float4)
__device__ __forceinline__ void copy32k(char* dst, const __half* __restrict__ src, int tid) {
    const float4* s = (const float4*)src;
    float4* d = (float4*)dst;
#pragma unroll
    for (int it = 0; it < 8; it++) d[it*256 + tid] = s[it*256 + tid];
}

// issue 32 independent LDGs for one tile into registers
__device__ __forceinline__ void stage_load(float r[32], const float* __restrict__ src, int tid) {
#pragma unroll
    for (int it = 0; it < 16; it++) {
        int idx = it*256 + tid;
        int vox = idx & 63;
        int k   = (idx >> 6) * 2;
        r[2*it]   = src[(size_t)k*NVOX + vox];
        r[2*it+1] = src[(size_t)(k+1)*NVOX + vox];
    }
}

// convert + store registers into a Y buffer (fp16 swizzled [vox][k])
__device__ __forceinline__ void stage_store(char* smb, uint32_t yoff, const float r[32], int tid) {
#pragma unroll
    for (int it = 0; it < 16; it++) {
        int idx = it*256 + tid;
        int vox = idx & 63;
        int k   = (idx >> 6) * 2;
        __half h0 = __float2half_rn(r[2*it]);
        __half h1 = __float2half_rn(r[2*it+1]);
        uint32_t hw = (uint32_t)__half_as_ushort(h0) | ((uint32_t)__half_as_ushort(h1) << 16);
        *(uint32_t*)(smb + yoff + swz(vox, k)) = hw;
    }
}

// ---------------------------------------------------------------------------
// Kernel 1: fused attention tile via mma.sync (fp16, pipelined staging).
// 256 thr = 8 warps; warp w owns channel rows [16w, 16w+16) == head w.
// ---------------------------------------------------------------------------
extern "C" __global__ void __launch_bounds__(256, 1)
attn_fused(const float* __restrict__ skip, const float* __restrict__ dec,
           const float* __restrict__ bq, const float* __restrict__ bk,
           const float* __restrict__ bv, const float* __restrict__ bo,
           float* __restrict__ out)
{
    extern __shared__ char smraw[];
    char* smb = (char*)(((uintptr_t)smraw + 1023) & ~(uintptr_t)1023);
    const uint32_t sb = smem_to_u32(smb);

    float* sp = (float*)(smb + OFF_SP);
    float* ms = (float*)(smb + OFF_MS);
    float* ls = (float*)(smb + OFF_LS);
    float* cs = (float*)(smb + OFF_CS);
    float* pp = (float*)(smb + OFF_PP);
    float* stg = (float*)(smb + OFF_STG);

    const int tid = threadIdx.x;
    const int w = tid >> 5, lane = tid & 31;
    const int tile = blockIdx.x, b = blockIdx.y;
    const int j4 = lane & 3;

    const size_t voxBase = (size_t)tile * TN;
    const float* decb  = dec  + (size_t)b*CC*NVOX + voxBase;
    const float* skipb = skip + (size_t)b*NCOND*CC*NVOX + voxBase;

    const uint32_t ybuf[2] = { sb + OFF_Y0, sb + OFF_Y1 };

    // prologue: Wq + Wk + Wv copies, X -> Y0 directly, cond0 LDGs into regs
    copy32k(smb + OFF_WA, g_w[0], tid);
    copy32k(smb + OFF_WK, g_w[1], tid);
    copy32k(smb + OFF_WV, g_w[2], tid);
    {
        float xr[32];
        stage_load(xr, decb, tid);
        stage_store(smb, OFF_Y0, xr, tid);
    }
    ms[tid] = -INFINITY; ms[tid+256] = -INFINITY;
    ls[tid] = 0.0f;      ls[tid+256] = 0.0f;

    float r[32];
    stage_load(r, skipb, tid);          // cond 0 (latency hidden by Q GEMM)
    __syncthreads();

    // ---- Q projection from Y0 ----
    float q[8][4];
#pragma unroll
    for (int nb = 0; nb < 8; nb++)
#pragma unroll
        for (int rr = 0; rr < 4; rr++) q[nb][rr] = 0.0f;
    gemm1(q, sb + OFF_WA, ybuf[0], w, lane);
    add_bias_frag(q, bq, w, lane);

    float oacc[8][4];
#pragma unroll
    for (int nb = 0; nb < 8; nb++)
#pragma unroll
        for (int rr = 0; rr < 4; rr++) oacc[nb][rr] = 0.0f;

    stage_store(smb, OFF_Y1, r, tid);   // cond0 -> Y1
    __syncthreads();

    // cond cd lives in ybuf[(cd+1)&1]; staging writes ybuf[cd&1]
#pragma unroll
    for (int cd = 0; cd < NCOND; cd++) {
        const uint32_t ycur = ybuf[(cd+1) & 1];

        if (cd < 3) stage_load(r, skipb + (size_t)(cd+1)*CC*NVOX, tid);

        // ---- fused K+V projection (LDG latency hides under these MMAs) ----
        float kf[8][4], vf[8][4];
#pragma unroll
        for (int nb = 0; nb < 8; nb++)
#pragma unroll
            for (int rr = 0; rr < 4; rr++) { kf[nb][rr] = 0.0f; vf[nb][rr] = 0.0f; }
        gemm1_kv(kf, vf, sb + OFF_WK, sb + OFF_WV, ycur, w, lane);
        add_bias_frag(kf, bk, w, lane);
        add_bias_frag(vf, bv, w, lane);

        // ---- scores (head w lives entirely in warp w) ----
#pragma unroll
        for (int nb = 0; nb < 8; nb++) {
            float pA = fmaf(q[nb][0], kf[nb][0], q[nb][2]*kf[nb][2]);
            float pB = fmaf(q[nb][1], kf[nb][1], q[nb][3]*kf[nb][3]);
#pragma unroll
            for (int off = 4; off <= 16; off <<= 1) {
                pA += __shfl_xor_sync(0xffffffffu, pA, off);
                pB += __shfl_xor_sync(0xffffffffu, pB, off);
            }
            if (lane < 4) {
                sp[w*TN + 8*nb + 2*lane]     = pA;
                sp[w*TN + 8*nb + 2*lane + 1] = pB;
            }
        }

        if (cd < 3) stage_store(smb, (cd & 1) ? OFF_Y1 : OFF_Y0, r, tid);
        __syncthreads();

        // online softmax state: 512 (head,voxel) items over 256 threads
#pragma unroll
        for (int t = tid; t < 512; t += 256) {
            float s  = sp[t] * 0.25f;                 // 1/sqrt(head_dim=16)
            float mo = ms[t];
            float mn = fmaxf(mo, s);
            float corr = __expf(mo - mn);
            float pv   = __expf(s - mn);
            ls[t] = ls[t]*corr + pv;
            ms[t] = mn;
            cs[t] = corr;
            pp[t] = pv;
        }
        __syncthreads();

        // ---- PV accumulate (registers only) ----
#pragma unroll
        for (int nb = 0; nb < 8; nb++) {
            int col = 8*nb + 2*j4;
            float c0 = cs[w*TN + col], c1 = cs[w*TN + col + 1];
            float p0 = pp[w*TN + col], p1 = pp[w*TN + col + 1];
            oacc[nb][0] = fmaf(oacc[nb][0], c0, p0*vf[nb][0]);
            oacc[nb][1] = fmaf(oacc[nb][1], c1, p1*vf[nb][1]);
            oacc[nb][2] = fmaf(oacc[nb][2], c0, p0*vf[nb][2]);
            oacc[nb][3] = fmaf(oacc[nb][3], c1, p1*vf[nb][3]);
        }
    }

    // ---- finalize attention output into Y0 (fp16), stage Wo ----
    // (all Y0 reads by gemm(cd=3) completed at the post-scores barrier)
    {
        const int r0 = 16*w + (lane >> 2);
#pragma unroll
        for (int nb = 0; nb < 8; nb++) {
            int col = 8*nb + 2*j4;
            float inv0 = 1.0f / ls[w*TN + col];
            float inv1 = 1.0f / ls[w*TN + col + 1];
            float o00 = oacc[nb][0] * inv0;
            float o01 = oacc[nb][1] * inv1;
            float o10 = oacc[nb][2] * inv0;
            float o11 = oacc[nb][3] * inv1;
#pragma unroll
            for (int e = 0; e < 4; e++) {
                float ov = (e == 0) ? o00 : (e == 1) ? o01 : (e == 2) ? o10 : o11;
                int rr = r0 + ((e >> 1) ? 8 : 0);
                int cc = col + (e & 1);
                *(__half*)(smb + OFF_Y0 + swz(cc, rr)) = __float2half_rn(ov);
            }
        }
    }
    copy32k(smb + OFF_WA, g_w[3], tid);   // Wo into slot A (Wq dead since prologue)
    __syncthreads();

    // ---- O projection ----
    float of[8][4];
#pragma unroll
    for (int nb = 0; nb < 8; nb++)
#pragma unroll
        for (int rr = 0; rr < 4; rr++) of[nb][rr] = 0.0f;
    gemm1(of, sb + OFF_WA, ybuf[0], w, lane);

    // stage O fragments to fp32 smem [128][72]
    {
        const int r0 = 16*w + (lane >> 2);
#pragma unroll
        for (int nb = 0; nb < 8; nb++) {
            int col = 8*nb + 2*j4;
            *(float2*)&stg[ r0      * STG_STRIDE + col] = make_float2(of[nb][0], of[nb][1]);
            *(float2*)&stg[(r0 + 8) * STG_STRIDE + col] = make_float2(of[nb][2], of[nb][3]);
        }
    }
    __syncthreads();

    // ---- epilogue: bias + residual + store + GN partials ----
    const int cy = tid >> 4, nx = tid & 15;
    const int co0 = cy*8, n0 = nx*4;
    float* outb = out + (size_t)b*CC*NVOX + voxBase;
    float s1 = 0.0f, s2 = 0.0f;
#pragma unroll
    for (int i = 0; i < 8; i++) {
        int co = co0 + i;
        float boc = __ldg(&bo[co]);
        float4 rv = *(const float4*)(decb + (size_t)co*NVOX + n0);
        float4 ov = *(const float4*)&stg[co*STG_STRIDE + n0];
        float u0 = ov.x + boc + rv.x;
        float u1 = ov.y + boc + rv.y;
        float u2 = ov.z + boc + rv.z;
        float u3 = ov.w + boc + rv.w;
        *(float4*)(outb + (size_t)co*NVOX + n0) = make_float4(u0, u1, u2, u3);
        s1 += (u0 + u1) + (u2 + u3);
        s2 += fmaf(u0, u0, u1*u1) + fmaf(u2, u2, u3*u3);
    }
#pragma unroll
    for (int off = 16; off; off >>= 1) {
        s1 += __shfl_xor_sync(0xffffffffu, s1, off);
        s2 += __shfl_xor_sync(0xffffffffu, s2, off);
    }
    if (lane == 0) {
        int slot = (b*NGROUPS + w)*NTILES + tile;   // warp w's 32 channels = GN group w
        g_sum[slot] = s1;
        g_sq[slot]  = s2;
    }
}

// ---------------------------------------------------------------------------
// Kernel 2: reduce per-tile partials into per-(batch,group) mean / rstd
// ---------------------------------------------------------------------------
extern "C" __global__ void gn_stats() {
    __shared__ float sh1[256], sh2[256];
    const int bg = blockIdx.x;        // 0..15
    const int tid = threadIdx.x;
    const float* ps = g_sum + bg*NTILES;
    const float* pq = g_sq  + bg*NTILES;
    float s1 = ps[tid] + ps[tid+256];
    float s2 = pq[tid] + pq[tid+256];
    sh1[tid] = s1; sh2[tid] = s2;
    __syncthreads();
    for (int off = 128; off; off >>= 1) {
        if (tid < off) { sh1[tid] += sh1[tid+off]; sh2[tid] += sh2[tid+off]; }
        __syncthreads();
    }
    if (tid == 0) {
        const float cnt = (float)(16 * NVOX);      // 524288
        float mean = sh1[0] / cnt;
        float var  = sh2[0] / cnt - mean*mean;
        g_stats[bg] = make_float2(mean, rsqrtf(var + 1e-5f));
    }
}

// ---------------------------------------------------------------------------
// Kernel 3: apply GroupNorm affine in place
// ---------------------------------------------------------------------------
extern "C" __global__ void gn_apply(float* __restrict__ out,
                                    const float* __restrict__ gamma,
                                    const float* __restrict__ beta) {
    size_t elem = ((size_t)blockIdx.x * blockDim.x + threadIdx.x) * 4;
    int b = (int)(elem >> 22);
    int c = (int)((elem >> 15) & 127);
    float2 st = g_stats[b*NGROUPS + (c >> 4)];
    float ga = __ldg(&gamma[c]), be = __ldg(&beta[c]);
    float4 v = *(float4*)(out + elem);
    float sc = st.y * ga;
    v.x = (v.x - st.x)*sc + be;
    v.y = (v.y - st.x)*sc + be;
    v.z = (v.z - st.x)*sc + be;
    v.w = (v.w - st.x)*sc + be;
    *(float4*)(out + elem) = v;
}

// ---------------------------------------------------------------------------
extern "C" void kernel_launch(void* const* d_in, const int* in_sizes, int n_in,
                              void* d_out, int out_size) {
    const float* skip  = (const float*)d_in[0];
    const float* dec   = (const float*)d_in[1];
    const float* wq    = (const float*)d_in[2];
    const float* wk    = (const float*)d_in[3];
    const float* wv    = (const float*)d_in[4];
    const float* bq    = (const float*)d_in[5];
    const float* bk    = (const float*)d_in[6];
    const float* bv    = (const float*)d_in[7];
    const float* wo    = (const float*)d_in[8];
    const float* bo    = (const float*)d_in[9];
    const float* gamma = (const float*)d_in[10];
    const float* beta  = (const float*)d_in[11];
    float* out = (float*)d_out;

    cudaFuncSetAttribute(attn_fused, cudaFuncAttributeMaxDynamicSharedMemorySize, SMEM_REQ);

    prep_w<<<256, 256>>>(wq, wk, wv, wo);
    dim3 grid(NTILES, NB);
    attn_fused<<<grid, 256, SMEM_REQ>>>(skip, dec, bq, bk, bv, bo, out);
    gn_stats<<<NB*NGROUPS, 256>>>();
    gn_apply<<<(NB*CC*NVOX/4)/256, 256>>>(out, gamma, beta);
}

// round 10
// speedup vs baseline: 2.8428x; 1.1431x over previous
#include <cuda_runtime.h>
#include <cuda_fp16.h>
#include <math.h>
#include <stdint.h>

// ---------------------------------------------------------------------------
// Problem constants
// ---------------------------------------------------------------------------
#define CC      128
#define TN      64
#define NCOND   4
#define NVOX    32768
#define NTILES  512
#define NB      2
#define NGROUPS 8
#define NUNITS  (NB*NTILES)     // 1024 (b, tile) work units
#define NCTA    148             // persistent CTAs (one per SM)

// smem byte offsets (from 1024-aligned base). One fp16 weight = 32KB.
#define OFF_WQ   0
#define OFF_WK   32768
#define OFF_WV   65536
#define OFF_WO   98304
#define OFF_Y0   131072     // activation buffer 0 [n=64][k=128] fp16 swizzled (16KB)
#define OFF_Y1   147456     // activation buffer 1 (16KB)
#define SMEM_REQ (163840 + 1024)

// ---------------------------------------------------------------------------
// global scratch (no allocations allowed)
// ---------------------------------------------------------------------------
__device__ __half g_w[4][CC*CC];    // Wq,Wk,Wv,Wo fp16 — swizzled [co][k]
__device__ float  g_sum[NB*NGROUPS*NTILES];
__device__ float  g_sq [NB*NGROUPS*NTILES];
__device__ float2 g_stats[NB*NGROUPS];

// ---------------------------------------------------------------------------
// PTX wrappers (plain sm_80-era ISA)
// ---------------------------------------------------------------------------
__device__ __forceinline__ uint32_t smem_to_u32(const void* p) {
    uint32_t a;
    asm("{ .reg .u64 t; cvta.to.shared.u64 t, %1; cvt.u32.u64 %0, t; }" : "=r"(a) : "l"(p));
    return a;
}
__device__ __forceinline__ void ldsm4(uint32_t r[4], uint32_t addr) {
    asm volatile("ldmatrix.sync.aligned.m8n8.x4.shared.b16 {%0,%1,%2,%3}, [%4];"
                 : "=r"(r[0]), "=r"(r[1]), "=r"(r[2]), "=r"(r[3]) : "r"(addr));
}
__device__ __forceinline__ void mma16816(float d[4], const uint32_t a[4],
                                         uint32_t b0, uint32_t b1) {
    asm volatile("mma.sync.aligned.m16n8k16.row.col.f32.f16.f16.f32 "
                 "{%0,%1,%2,%3}, {%4,%5,%6,%7}, {%8,%9}, {%0,%1,%2,%3};"
                 : "+f"(d[0]), "+f"(d[1]), "+f"(d[2]), "+f"(d[3])
                 : "r"(a[0]), "r"(a[1]), "r"(a[2]), "r"(a[3]), "r"(b0), "r"(b1));
}

// swizzled byte offset inside a [rows][128] fp16 tile with 256B rows
__device__ __forceinline__ uint32_t swz(int row, int k) {
    return (uint32_t)(row * 256 + ((((k >> 3) ^ (row & 7)) & 15) << 4) + (k & 7) * 2);
}

// ---------------------------------------------------------------------------
// single-pass fp16 GEMM: acc[nb][4] += W[16w:16w+16, :] @ Y[:, :].T
// ---------------------------------------------------------------------------
__device__ __forceinline__ void gemm1(float acc[8][4], uint32_t wa, uint32_t y,
                                      int w, int lane) {
    const int row  = lane & 15;
    const int half = lane >> 4;
#pragma unroll
    for (int kc = 0; kc < 8; kc++) {
        const uint32_t uoff = (uint32_t)((((2*kc + half) ^ (row & 7)) & 15) << 4);
        uint32_t A[4];
        ldsm4(A, wa + (uint32_t)(16*w + row)*256 + uoff);
#pragma unroll
        for (int nb2 = 0; nb2 < 4; nb2++) {
            uint32_t B[4];
            ldsm4(B, y + (uint32_t)(16*nb2 + row)*256 + uoff);
            mma16816(acc[2*nb2],   A, B[0], B[2]);
            mma16816(acc[2*nb2+1], A, B[1], B[3]);
        }
    }
}

// fused K+V GEMM: B fragments loaded once
__device__ __forceinline__ void gemm1_kv(float kf[8][4], float vf[8][4],
                                         uint32_t wk_, uint32_t wv_, uint32_t y,
                                         int w, int lane) {
    const int row  = lane & 15;
    const int half = lane >> 4;
#pragma unroll
    for (int kc = 0; kc < 8; kc++) {
        const uint32_t uoff = (uint32_t)((((2*kc + half) ^ (row & 7)) & 15) << 4);
        const uint32_t arow = (uint32_t)(16*w + row)*256 + uoff;
        uint32_t KA[4], VA[4];
        ldsm4(KA, wk_ + arow);
        ldsm4(VA, wv_ + arow);
#pragma unroll
        for (int nb2 = 0; nb2 < 4; nb2++) {
            uint32_t B[4];
            ldsm4(B, y + (uint32_t)(16*nb2 + row)*256 + uoff);
            mma16816(kf[2*nb2],   KA, B[0], B[2]);
            mma16816(kf[2*nb2+1], KA, B[1], B[3]);
            mma16816(vf[2*nb2],   VA, B[0], B[2]);
            mma16816(vf[2*nb2+1], VA, B[1], B[3]);
        }
    }
}

__device__ __forceinline__ void add_bias_frag(float acc[8][4], const float* __restrict__ bias,
                                              int w, int lane) {
    float b0 = __ldg(&bias[16*w + (lane >> 2)]);
    float b1 = __ldg(&bias[16*w + (lane >> 2) + 8]);
#pragma unroll
    for (int nb = 0; nb < 8; nb++) {
        acc[nb][0] += b0; acc[nb][1] += b0;
        acc[nb][2] += b1; acc[nb][3] += b1;
    }
}

// ---------------------------------------------------------------------------
// Kernel 0: weights -> fp16, pre-swizzled [co][k] (runs once)
// ---------------------------------------------------------------------------
extern "C" __global__ void prep_w(const float* __restrict__ wq, const float* __restrict__ wk,
                                  const float* __restrict__ wv, const float* __restrict__ wo) {
    int idx = blockIdx.x * 256 + threadIdx.x;   // 0..65535
    int m = idx >> 14, e = idx & 16383;
    int co = e >> 7, k = e & 127;
    const float* src = (m == 0) ? wq : (m == 1) ? wk : (m == 2) ? wv : wo;
    g_w[m][swz(co, k) >> 1] = __float2half_rn(src[e]);
}

// ---------------------------------------------------------------------------
// staging helpers
// ---------------------------------------------------------------------------
__device__ __forceinline__ void copy32k(char* dst, const __half* __restrict__ src, int tid) {
    const float4* s = (const float4*)src;
    float4* d = (float4*)dst;
#pragma unroll
    for (int it = 0; it < 8; it++) d[it*256 + tid] = s[it*256 + tid];
}

__device__ __forceinline__ void stage_load(float r[32], const float* __restrict__ src, int tid) {
#pragma unroll
    for (int it = 0; it < 16; it++) {
        int idx = it*256 + tid;
        int vox = idx & 63;
        int k   = (idx >> 6) * 2;
        r[2*it]   = src[(size_t)k*NVOX + vox];
        r[2*it+1] = src[(size_t)(k+1)*NVOX + vox];
    }
}

__device__ __forceinline__ void stage_store(char* smb, uint32_t yoff, const float r[32], int tid) {
#pragma unroll
    for (int it = 0; it < 16; it++) {
        int idx = it*256 + tid;
        int vox = idx & 63;
        int k   = (idx >> 6) * 2;
        __half h0 = __float2half_rn(r[2*it]);
        __half h1 = __float2half_rn(r[2*it+1]);
        uint32_t hw = (uint32_t)__half_as_ushort(h0) | ((uint32_t)__half_as_ushort(h1) << 16);
        *(uint32_t*)(smb + yoff + swz(vox, k)) = hw;
    }
}

// ---------------------------------------------------------------------------
// Kernel 1: persistent fused attention. 148 CTAs x 256 thr; each CTA owns all
// 4 weights in smem and loops over (b, tile) units. Softmax is warp-local:
// lane (4*nb + j) owns online-softmax state for cols (8nb+2j, 8nb+2j+1);
// corr/p broadcast by shuffle. Epilogue writes O fragments directly to gmem.
// ---------------------------------------------------------------------------
extern "C" __global__ void __launch_bounds__(256, 1)
attn_fused(const float* __restrict__ skip, const float* __restrict__ dec,
           const float* __restrict__ bq, const float* __restrict__ bk,
           const float* __restrict__ bv, const float* __restrict__ bo,
           float* __restrict__ out)
{
    extern __shared__ char smraw[];
    char* smb = (char*)(((uintptr_t)smraw + 1023) & ~(uintptr_t)1023);
    const uint32_t sb = smem_to_u32(smb);

    const int tid = threadIdx.x;
    const int w = tid >> 5, lane = tid & 31;
    const int j4 = lane & 3;
    const int myNb = lane >> 2;          // softmax-state owner: cols (8*myNb+2*j4, +1)... per-lane
    const uint32_t ybuf[2] = { sb + OFF_Y0, sb + OFF_Y1 };

    // one-time weight residency
    copy32k(smb + OFF_WQ, g_w[0], tid);
    copy32k(smb + OFF_WK, g_w[1], tid);
    copy32k(smb + OFF_WV, g_w[2], tid);
    copy32k(smb + OFF_WO, g_w[3], tid);

    int u = blockIdx.x;
    float r[32];
    if (u < NUNITS) {
        int b = u >> 9, tile = u & 511;
        const float* decb  = dec  + (size_t)b*CC*NVOX + (size_t)tile*TN;
        const float* skipb = skip + (size_t)b*NCOND*CC*NVOX + (size_t)tile*TN;
        float xr[32];
        stage_load(xr, decb, tid);
        stage_store(smb, OFF_Y0, xr, tid);
        stage_load(r, skipb, tid);       // cond 0
    }
    __syncthreads();                     // weights + Y0 ready

    for (; u < NUNITS; u += NCTA) {
        const int b = u >> 9, tile = u & 511;
        const size_t voxBase = (size_t)tile * TN;
        const float* decb  = dec  + (size_t)b*CC*NVOX + voxBase;
        const float* skipb = skip + (size_t)b*NCOND*CC*NVOX + voxBase;

        // ---- Q projection from Y0 ----
        float q[8][4];
#pragma unroll
        for (int nb = 0; nb < 8; nb++)
#pragma unroll
            for (int rr = 0; rr < 4; rr++) q[nb][rr] = 0.0f;
        gemm1(q, sb + OFF_WQ, ybuf[0], w, lane);
        add_bias_frag(q, bq, w, lane);

        float oacc[8][4];
#pragma unroll
        for (int nb = 0; nb < 8; nb++)
#pragma unroll
            for (int rr = 0; rr < 4; rr++) oacc[nb][rr] = 0.0f;

        // warp-local softmax state (this lane owns cols 8*myNb+2*j4, +1)
        float mA = -INFINITY, lA = 0.0f, mB = -INFINITY, lB = 0.0f;

        stage_store(smb, OFF_Y1, r, tid);   // cond0 -> Y1
        __syncthreads();

        // cond cd lives in ybuf[(cd+1)&1]; staging writes ybuf[cd&1]
#pragma unroll
        for (int cd = 0; cd < NCOND; cd++) {
            const uint32_t ycur = ybuf[(cd+1) & 1];
            if (cd < 3) stage_load(r, skipb + (size_t)(cd+1)*CC*NVOX, tid);

            float kf[8][4], vf[8][4];
#pragma unroll
            for (int nb = 0; nb < 8; nb++)
#pragma unroll
                for (int rr = 0; rr < 4; rr++) { kf[nb][rr] = 0.0f; vf[nb][rr] = 0.0f; }
            gemm1_kv(kf, vf, sb + OFF_WK, sb + OFF_WV, ycur, w, lane);
            add_bias_frag(kf, bk, w, lane);
            add_bias_frag(vf, bv, w, lane);

            // scores: reduce dot over 16 head channels (regs [0]/[2] + lanes>>2)
            float sOwnA = 0.0f, sOwnB = 0.0f;
#pragma unroll
            for (int nb = 0; nb < 8; nb++) {
                float pA = fmaf(q[nb][0], kf[nb][0], q[nb][2]*kf[nb][2]);
                float pB = fmaf(q[nb][1], kf[nb][1], q[nb][3]*kf[nb][3]);
#pragma unroll
                for (int off = 4; off <= 16; off <<= 1) {
                    pA += __shfl_xor_sync(0xffffffffu, pA, off);
                    pB += __shfl_xor_sync(0xffffffffu, pB, off);
                }
                if (myNb == nb) { sOwnA = pA; sOwnB = pB; }
            }

            // online-softmax state update for owned cols (4 expf/thread/iter)
            sOwnA *= 0.25f;  sOwnB *= 0.25f;          // 1/sqrt(head_dim=16)
            float mnA = fmaxf(mA, sOwnA);
            float corrA = __expf(mA - mnA);
            float pEA   = __expf(sOwnA - mnA);
            lA = lA*corrA + pEA;  mA = mnA;
            float mnB = fmaxf(mB, sOwnB);
            float corrB = __expf(mB - mnB);
            float pEB   = __expf(sOwnB - mnB);
            lB = lB*corrB + pEB;  mB = mnB;

            // PV accumulate: fetch corr/p for each nb from owning lane
#pragma unroll
            for (int nb = 0; nb < 8; nb++) {
                int srcl = nb*4 + j4;
                float c0 = __shfl_sync(0xffffffffu, corrA, srcl);
                float p0 = __shfl_sync(0xffffffffu, pEA,   srcl);
                float c1 = __shfl_sync(0xffffffffu, corrB, srcl);
                float p1 = __shfl_sync(0xffffffffu, pEB,   srcl);
                oacc[nb][0] = fmaf(oacc[nb][0], c0, p0*vf[nb][0]);
                oacc[nb][1] = fmaf(oacc[nb][1], c1, p1*vf[nb][1]);
                oacc[nb][2] = fmaf(oacc[nb][2], c0, p0*vf[nb][2]);
                oacc[nb][3] = fmaf(oacc[nb][3], c1, p1*vf[nb][3]);
            }

            if (cd < 3) {
                stage_store(smb, (cd & 1) ? OFF_Y1 : OFF_Y0, r, tid);
                __syncthreads();
            }
        }

        // ---- attention output -> Y1 (fp16) ----
        {
            const int r0 = 16*w + (lane >> 2);
#pragma unroll
            for (int nb = 0; nb < 8; nb++) {
                int srcl = nb*4 + j4;
                float inv0 = 1.0f / __shfl_sync(0xffffffffu, lA, srcl);
                float inv1 = 1.0f / __shfl_sync(0xffffffffu, lB, srcl);
                int col = 8*nb + 2*j4;
                *(__half*)(smb + OFF_Y1 + swz(col,     r0    )) = __float2half_rn(oacc[nb][0]*inv0);
                *(__half*)(smb + OFF_Y1 + swz(col + 1, r0    )) = __float2half_rn(oacc[nb][1]*inv1);
                *(__half*)(smb + OFF_Y1 + swz(col,     r0 + 8)) = __float2half_rn(oacc[nb][2]*inv0);
                *(__half*)(smb + OFF_Y1 + swz(col + 1, r0 + 8)) = __float2half_rn(oacc[nb][3]*inv1);
            }
        }
        __syncthreads();                 // all attention writes visible; Y0 free

        // ---- next unit X staging overlaps O projection ----
        const bool more = (u + NCTA < NUNITS);
        float xr[32];
        if (more) {
            int un = u + NCTA;
            int bn = un >> 9, tn = un & 511;
            stage_load(xr, dec + (size_t)bn*CC*NVOX + (size_t)tn*TN, tid);
        }

        float of[8][4];
#pragma unroll
        for (int nb = 0; nb < 8; nb++)
#pragma unroll
            for (int rr = 0; rr < 4; rr++) of[nb][rr] = 0.0f;
        gemm1(of, sb + OFF_WO, ybuf[1], w, lane);

        if (more) stage_store(smb, OFF_Y0, xr, tid);

        // ---- fragment-direct epilogue: bias + residual + store + GN ----
        {
            const int r0 = 16*w + (lane >> 2);
            const float bo0 = __ldg(&bo[r0]);
            const float bo1 = __ldg(&bo[r0 + 8]);
            float* outb = out + (size_t)b*CC*NVOX + voxBase;
            float s1 = 0.0f, s2 = 0.0f;
#pragma unroll
            for (int nb = 0; nb < 8; nb++) {
                int col = 8*nb + 2*j4;
                float2 rv0 = *(const float2*)(decb + (size_t)r0*NVOX + col);
                float2 rv1 = *(const float2*)(decb + (size_t)(r0+8)*NVOX + col);
                float u0 = of[nb][0] + bo0 + rv0.x;
                float u1 = of[nb][1] + bo0 + rv0.y;
                float u2 = of[nb][2] + bo1 + rv1.x;
                float u3 = of[nb][3] + bo1 + rv1.y;
                *(float2*)(outb + (size_t)r0*NVOX + col)     = make_float2(u0, u1);
                *(float2*)(outb + (size_t)(r0+8)*NVOX + col) = make_float2(u2, u3);
                s1 += (u0 + u1) + (u2 + u3);
                s2 += fmaf(u0, u0, u1*u1) + fmaf(u2, u2, u3*u3);
            }
#pragma unroll
            for (int off = 16; off; off >>= 1) {
                s1 += __shfl_xor_sync(0xffffffffu, s1, off);
                s2 += __shfl_xor_sync(0xffffffffu, s2, off);
            }
            if (lane == 0) {
                int slot = (b*NGROUPS + w)*NTILES + tile;   // warp w == GN group w
                g_sum[slot] = s1;
                g_sq[slot]  = s2;
            }
        }

        if (more) {
            int un = u + NCTA;
            int bn = un >> 9, tn = un & 511;
            stage_load(r, skip + (size_t)bn*NCOND*CC*NVOX + (size_t)tn*TN, tid);  // cond0
        }
        __syncthreads();                 // Y0(next) ready; O gemm reads done
    }
}

// ---------------------------------------------------------------------------
// Kernel 2: reduce per-tile partials into per-(batch,group) mean / rstd
// ---------------------------------------------------------------------------
extern "C" __global__ void gn_stats() {
    __shared__ float sh1[256], sh2[256];
    const int bg = blockIdx.x;        // 0..15
    const int tid = threadIdx.x;
    const float* ps = g_sum + bg*NTILES;
    const float* pq = g_sq  + bg*NTILES;
    float s1 = ps[tid] + ps[tid+256];
    float s2 = pq[tid] + pq[tid+256];
    sh1[tid] = s1; sh2[tid] = s2;
    __syncthreads();
    for (int off = 128; off; off >>= 1) {
        if (tid < off) { sh1[tid] += sh1[tid+off]; sh2[tid] += sh2[tid+off]; }
        __syncthreads();
    }
    if (tid == 0) {
        const float cnt = (float)(16 * NVOX);      // 524288
        float mean = sh1[0] / cnt;
        float var  = sh2[0] / cnt - mean*mean;
        g_stats[bg] = make_float2(mean, rsqrtf(var + 1e-5f));
    }
}

// ---------------------------------------------------------------------------
// Kernel 3: apply GroupNorm affine in place
// ---------------------------------------------------------------------------
extern "C" __global__ void gn_apply(float* __restrict__ out,
                                    const float* __restrict__ gamma,
                                    const float* __restrict__ beta) {
    size_t elem = ((size_t)blockIdx.x * blockDim.x + threadIdx.x) * 4;
    int b = (int)(elem >> 22);
    int c = (int)((elem >> 15) & 127);
    float2 st = g_stats[b*NGROUPS + (c >> 4)];
    float ga = __ldg(&gamma[c]), be = __ldg(&beta[c]);
    float4 v = *(float4*)(out + elem);
    float sc = st.y * ga;
    v.x = (v.x - st.x)*sc + be;
    v.y = (v.y - st.x)*sc + be;
    v.z = (v.z - st.x)*sc + be;
    v.w = (v.w - st.x)*sc + be;
    *(float4*)(out + elem) = v;
}

// ---------------------------------------------------------------------------
extern "C" void kernel_launch(void* const* d_in, const int* in_sizes, int n_in,
                              void* d_out, int out_size) {
    const float* skip  = (const float*)d_in[0];
    const float* dec   = (const float*)d_in[1];
    const float* wq    = (const float*)d_in[2];
    const float* wk    = (const float*)d_in[3];
    const float* wv    = (const float*)d_in[4];
    const float* bq    = (const float*)d_in[5];
    const float* bk    = (const float*)d_in[6];
    const float* bv    = (const float*)d_in[7];
    const float* wo    = (const float*)d_in[8];
    const float* bo    = (const float*)d_in[9];
    const float* gamma = (const float*)d_in[10];
    const float* beta  = (const float*)d_in[11];
    float* out = (float*)d_out;

    cudaFuncSetAttribute(attn_fused, cudaFuncAttributeMaxDynamicSharedMemorySize, SMEM_REQ);

    prep_w<<<256, 256>>>(wq, wk, wv, wo);
    attn_fused<<<NCTA, 256, SMEM_REQ>>>(skip, dec, bq, bk, bv, bo, out);
    gn_stats<<<NB*NGROUPS, 256>>>();
    gn_apply<<<(NB*CC*NVOX/4)/256, 256>>>(out, gamma, beta);
}